// round 1
// baseline (speedup 1.0000x reference)
#include <cuda_runtime.h>
#include <math.h>

#define N_NODES   65536
#define HIDDEN    256
#define NUM_GRAPHS 64
#define VOCAB     50000
#define LAYERS    3
#define MAX_E     1114112   // 1048576 edges + 65536 self loops
#define NEG_SLOPE 0.2f
#define EPS_SM    1e-16f

// ---------------- scratch (device globals; no cudaMalloc allowed) ----------------
__device__ float g_x[N_NODES * HIDDEN];   // node features (layer input / output)
__device__ float g_h[N_NODES * HIDDEN];   // h = x @ Wg
__device__ float g_t[N_NODES * HIDDEN];   // aggregated output (pre second GEMM)
__device__ float g_es[N_NODES];
__device__ float g_ed[N_NODES];
__device__ int   g_deg[N_NODES];
__device__ int   g_off[N_NODES + 1];
__device__ int   g_cur[N_NODES];
__device__ int   g_csr[MAX_E];            // src node id per incoming edge, grouped by dst
__device__ float g_pool[NUM_GRAPHS * HIDDEN];
__device__ int   g_gcnt[NUM_GRAPHS];

// ---------------- CSR build ----------------
__global__ void k_init_deg() {
    int i = blockIdx.x * blockDim.x + threadIdx.x;
    if (i < N_NODES) g_deg[i] = 1;  // self loop
}

__global__ void k_count_deg(const int* __restrict__ dst, int E) {
    int e = blockIdx.x * blockDim.x + threadIdx.x;
    if (e < E) atomicAdd(&g_deg[dst[e]], 1);
}

// single-block scan: 1024 threads x 64 elements each
__global__ void k_scan() {
    __shared__ int sh[1024];
    int t = threadIdx.x;
    int base = t * 64;
    int s = 0;
    for (int j = 0; j < 64; j++) s += g_deg[base + j];
    sh[t] = s;
    __syncthreads();
    for (int d = 1; d < 1024; d <<= 1) {
        int v = (t >= d) ? sh[t - d] : 0;
        __syncthreads();
        sh[t] += v;
        __syncthreads();
    }
    int run = sh[t] - s;  // exclusive prefix of this chunk
    for (int j = 0; j < 64; j++) {
        g_off[base + j] = run;
        run += g_deg[base + j];
    }
    if (t == 1023) g_off[N_NODES] = run;
}

__global__ void k_init_cur() {
    int i = blockIdx.x * blockDim.x + threadIdx.x;
    if (i < N_NODES) g_cur[i] = g_off[i];
}

__global__ void k_fill(const int* __restrict__ src, const int* __restrict__ dst, int E) {
    int e = blockIdx.x * blockDim.x + threadIdx.x;
    if (e < E) {
        int pos = atomicAdd(&g_cur[dst[e]], 1);
        g_csr[pos] = src[e];
    }
}

__global__ void k_selfloop() {
    int i = blockIdx.x * blockDim.x + threadIdx.x;
    if (i < N_NODES) g_csr[g_off[i + 1] - 1] = i;  // self edge in last slot
}

// ---------------- embedding gather ----------------
__global__ void k_embed(const int* __restrict__ nodes, const float* __restrict__ emb) {
    int idx = blockIdx.x * blockDim.x + threadIdx.x;
    if (idx < N_NODES * HIDDEN) {
        int n = idx >> 8;
        int c = idx & 255;
        g_x[idx] = emb[(size_t)nodes[n] * HIDDEN + c];
    }
}

// ---------------- tiled FP32 GEMM: C[M,N] = A[M,K] @ B[K,N] (+bias) ----------------
#define BM 64
#define BN 64
#define BK 16
__global__ void k_gemm(const float* __restrict__ A, const float* __restrict__ B,
                       const float* __restrict__ bias, float* __restrict__ C,
                       int M, int N, int K) {
    __shared__ float As[BM][BK];
    __shared__ float Bs[BK][BN + 1];
    int tid = threadIdx.y * 16 + threadIdx.x;
    int m0 = blockIdx.y * BM, n0 = blockIdx.x * BN;
    float acc[4][4] = {};
    for (int k0 = 0; k0 < K; k0 += BK) {
#pragma unroll
        for (int r = 0; r < 4; r++) {
            int e = tid + r * 256;
            int m = e / BK, k = e % BK;
            As[m][k] = (m0 + m < M) ? A[(size_t)(m0 + m) * K + k0 + k] : 0.f;
        }
#pragma unroll
        for (int r = 0; r < 4; r++) {
            int e = tid + r * 256;
            int k = e / BN, n = e % BN;
            Bs[k][n] = (n0 + n < N) ? B[(size_t)(k0 + k) * N + n0 + n] : 0.f;
        }
        __syncthreads();
#pragma unroll
        for (int kk = 0; kk < BK; kk++) {
            float ra[4], rb[4];
#pragma unroll
            for (int i = 0; i < 4; i++) ra[i] = As[threadIdx.y * 4 + i][kk];
#pragma unroll
            for (int j = 0; j < 4; j++) rb[j] = Bs[kk][threadIdx.x * 4 + j];
#pragma unroll
            for (int i = 0; i < 4; i++)
#pragma unroll
                for (int j = 0; j < 4; j++) acc[i][j] += ra[i] * rb[j];
        }
        __syncthreads();
    }
#pragma unroll
    for (int i = 0; i < 4; i++) {
        int m = m0 + threadIdx.y * 4 + i;
        if (m >= M) continue;
#pragma unroll
        for (int j = 0; j < 4; j++) {
            int n = n0 + threadIdx.x * 4 + j;
            if (n >= N) continue;
            float v = acc[i][j];
            if (bias) v += bias[n];
            C[(size_t)m * N + n] = v;
        }
    }
}

// ---------------- attention scalar dots: es = h @ a_src, ed = h @ a_dst ----------------
__global__ void k_dots(const float* __restrict__ h, const float* __restrict__ a_s,
                       const float* __restrict__ a_d) {
    int w = (blockIdx.x * blockDim.x + threadIdx.x) >> 5;
    int lane = threadIdx.x & 31;
    if (w >= N_NODES) return;
    const float* row = h + (size_t)w * HIDDEN;
    float s = 0.f, d = 0.f;
#pragma unroll
    for (int j = 0; j < 8; j++) {
        int c = lane + 32 * j;
        float v = row[c];
        s += v * a_s[c];
        d += v * a_d[c];
    }
#pragma unroll
    for (int o = 16; o; o >>= 1) {
        s += __shfl_xor_sync(0xffffffffu, s, o);
        d += __shfl_xor_sync(0xffffffffu, d, o);
    }
    if (lane == 0) { g_es[w] = s; g_ed[w] = d; }
}

__device__ __forceinline__ float leaky(float v) {
    return v > 0.f ? v : NEG_SLOPE * v;
}

// ---------------- GAT aggregation: one warp per dst node ----------------
__global__ void k_agg(const float* __restrict__ h, const float* __restrict__ bg,
                      float* __restrict__ out) {
    int w = (blockIdx.x * blockDim.x + threadIdx.x) >> 5;
    int lane = threadIdx.x & 31;
    if (w >= N_NODES) return;
    int b0 = g_off[w], b1 = g_off[w + 1];
    float edv = g_ed[w];
    // pass 1: segment max
    float m = -1e30f;
    for (int e = b0 + lane; e < b1; e += 32)
        m = fmaxf(m, leaky(g_es[g_csr[e]] + edv));
#pragma unroll
    for (int o = 16; o; o >>= 1) m = fmaxf(m, __shfl_xor_sync(0xffffffffu, m, o));
    // pass 2: denom
    float s = 0.f;
    for (int e = b0 + lane; e < b1; e += 32)
        s += __expf(leaky(g_es[g_csr[e]] + edv) - m);
#pragma unroll
    for (int o = 16; o; o >>= 1) s += __shfl_xor_sync(0xffffffffu, s, o);
    float inv = 1.f / (s + EPS_SM);
    // pass 3: weighted feature sum (all lanes walk all edges; lane owns 8 channels)
    float acc[8] = {};
    for (int e = b0; e < b1; e++) {
        int src = g_csr[e];
        float a = __expf(leaky(g_es[src] + edv) - m) * inv;
        const float* hr = h + (size_t)src * HIDDEN;
#pragma unroll
        for (int j = 0; j < 8; j++) acc[j] += a * hr[lane + 32 * j];
    }
#pragma unroll
    for (int j = 0; j < 8; j++) {
        int c = lane + 32 * j;
        out[(size_t)w * HIDDEN + c] = fmaxf(acc[j] + bg[c], 0.f);  // +bg, relu
    }
}

// ---------------- mean pool ----------------
__global__ void k_pool_zero() {
    int i = blockIdx.x * blockDim.x + threadIdx.x;
    if (i < NUM_GRAPHS * HIDDEN) g_pool[i] = 0.f;
    if (i < NUM_GRAPHS) g_gcnt[i] = 0;
}

__global__ void k_counts(const int* __restrict__ batch) {
    int i = blockIdx.x * blockDim.x + threadIdx.x;
    if (i < N_NODES) atomicAdd(&g_gcnt[batch[i]], 1);
}

__global__ void k_pool(const float* __restrict__ x, const int* __restrict__ batch) {
    __shared__ int shb[256];
    int c = threadIdx.x;
    int n0 = blockIdx.x * 256;
    shb[c] = batch[n0 + c];
    __syncthreads();
    float acc = 0.f;
    int cg = shb[0];
    for (int n = 0; n < 256; n++) {
        int g = shb[n];
        if (g != cg) {
            atomicAdd(&g_pool[cg * HIDDEN + c], acc);
            acc = 0.f;
            cg = g;
        }
        acc += x[(size_t)(n0 + n) * HIDDEN + c];
    }
    atomicAdd(&g_pool[cg * HIDDEN + c], acc);
}

__global__ void k_mean() {
    int i = blockIdx.x * blockDim.x + threadIdx.x;
    if (i < NUM_GRAPHS * HIDDEN) {
        float cnt = (float)g_gcnt[i >> 8];
        g_pool[i] /= fmaxf(cnt, 1.f);
    }
}

// ---------------- launch ----------------
extern "C" void kernel_launch(void* const* d_in, const int* in_sizes, int n_in,
                              void* d_out, int out_size) {
    const int*   nodes = (const int*)d_in[0];
    const int*   eidx  = (const int*)d_in[1];
    const int*   batch = (const int*)d_in[2];
    const float* emb   = (const float*)d_in[3];
    const float* Wg    = (const float*)d_in[4];
    const float* a_src = (const float*)d_in[5];
    const float* a_dst = (const float*)d_in[6];
    const float* bg    = (const float*)d_in[7];
    const float* Wl    = (const float*)d_in[8];
    const float* bl    = (const float*)d_in[9];
    const float* Wout  = (const float*)d_in[10];
    const float* bout  = (const float*)d_in[11];

    const int E = in_sizes[1] / 2;
    const int* src = eidx;
    const int* dst = eidx + E;

    float *dx, *dh, *dt, *dpool;
    cudaGetSymbolAddress((void**)&dx, g_x);
    cudaGetSymbolAddress((void**)&dh, g_h);
    cudaGetSymbolAddress((void**)&dt, g_t);
    cudaGetSymbolAddress((void**)&dpool, g_pool);

    // CSR build
    k_init_deg<<<N_NODES / 256, 256>>>();
    k_count_deg<<<(E + 255) / 256, 256>>>(dst, E);
    k_scan<<<1, 1024>>>();
    k_init_cur<<<N_NODES / 256, 256>>>();
    k_fill<<<(E + 255) / 256, 256>>>(src, dst, E);
    k_selfloop<<<N_NODES / 256, 256>>>();

    // embedding
    k_embed<<<(N_NODES * HIDDEN) / 256, 256>>>(nodes, emb);

    dim3 blk(16, 16);
    dim3 grd_node(HIDDEN / BN, N_NODES / BM);
    const int warp_blocks = (N_NODES * 32) / 256;

    for (int l = 0; l < LAYERS; l++) {
        const float* Wg_l = Wg + (size_t)l * HIDDEN * HIDDEN;
        const float* Wl_l = Wl + (size_t)l * HIDDEN * HIDDEN;
        // h = x @ Wg[l]
        k_gemm<<<grd_node, blk>>>(dx, Wg_l, nullptr, dh, N_NODES, HIDDEN, HIDDEN);
        // es/ed
        k_dots<<<warp_blocks, 256>>>(dh, a_src + l * HIDDEN, a_dst + l * HIDDEN);
        // segment softmax + aggregation (+bg, relu)
        k_agg<<<warp_blocks, 256>>>(dh, bg + l * HIDDEN, dt);
        // x = t @ Wl[l] + bl[l]
        k_gemm<<<grd_node, blk>>>(dt, Wl_l, bl + l * HIDDEN, dx, N_NODES, HIDDEN, HIDDEN);
    }

    // mean pool
    k_pool_zero<<<(NUM_GRAPHS * HIDDEN + 255) / 256, 256>>>();
    k_counts<<<N_NODES / 256, 256>>>(batch);
    k_pool<<<N_NODES / 256, 256>>>(dx, batch);
    k_mean<<<(NUM_GRAPHS * HIDDEN + 255) / 256, 256>>>();

    // out[64, 50000] = pooled @ Wout + bout
    dim3 grd_out((VOCAB + BN - 1) / BN, (NUM_GRAPHS + BM - 1) / BM);
    k_gemm<<<grd_out, blk>>>(dpool, Wout, bout, (float*)d_out,
                             NUM_GRAPHS, VOCAB, HIDDEN);
}

// round 3
// speedup vs baseline: 1.9676x; 1.9676x over previous
#include <cuda_runtime.h>
#include <cstdint>
#include <math.h>

#define N_NODES   65536
#define HIDDEN    256
#define NUM_GRAPHS 64
#define VOCAB     50000
#define LAYERS    3
#define MAX_E     1114112
#define NEG_SLOPE 0.2f
#define EPS_SM    1e-16f

// ---------------- scratch ----------------
__device__ float g_x[N_NODES * HIDDEN];
__device__ float g_h[N_NODES * HIDDEN];
__device__ float g_t[N_NODES * HIDDEN];
__device__ float g_WT[2 * LAYERS * HIDDEN * HIDDEN];  // [0..2]=Wg^T, [3..5]=Wl^T
__device__ float g_es[N_NODES];
__device__ float g_ed[N_NODES];
__device__ int   g_deg[N_NODES];
__device__ int   g_off[N_NODES + 1];
__device__ int   g_cur[N_NODES];
__device__ int   g_csr[MAX_E];
__device__ float g_pool[NUM_GRAPHS * HIDDEN];
__device__ int   g_gcnt[NUM_GRAPHS];

__device__ __forceinline__ uint32_t cvt_tf32(float v) {
    uint32_t r;
    asm("cvt.rna.tf32.f32 %0, %1;" : "=r"(r) : "f"(v));
    return r;
}

__device__ __forceinline__ void mma_tf32(float* c, const uint32_t* a,
                                         uint32_t b0, uint32_t b1) {
    asm volatile(
        "mma.sync.aligned.m16n8k8.row.col.f32.tf32.tf32.f32 "
        "{%0,%1,%2,%3}, {%4,%5,%6,%7}, {%8,%9}, {%0,%1,%2,%3};\n"
        : "+f"(c[0]), "+f"(c[1]), "+f"(c[2]), "+f"(c[3])
        : "r"(a[0]), "r"(a[1]), "r"(a[2]), "r"(a[3]), "r"(b0), "r"(b1));
}

// ---------------- weight transpose: WT[n*256+k] = W[k*256+n] ----------------
__global__ void k_transpose(const float* __restrict__ Wg, const float* __restrict__ Wl) {
    int i = blockIdx.x * 256 + threadIdx.x;
    int which = i / (LAYERS * HIDDEN * HIDDEN);
    int rem = i % (LAYERS * HIDDEN * HIDDEN);
    int l = rem / (HIDDEN * HIDDEN);
    int nk = rem % (HIDDEN * HIDDEN);
    int n = nk >> 8, k = nk & 255;
    const float* W = which ? Wl : Wg;
    g_WT[i] = W[l * HIDDEN * HIDDEN + k * HIDDEN + n];
}

// ============ tf32 mma.sync GEMM: C[65536,256] = A[65536,256] @ WT^T ============
// CTA: 128 rows x 256 cols (full N), BK=32, double-buffered fragment-major SMEM.
// 512 threads = 16 warps (4m x 4n), warp tile 32x64.
// SMEM stage: A 4096 floats (frag-major) + B 8192 floats = 12288 floats; x2 stages.
#define STG_F 12288
#define SMEM_MMA (2 * STG_F * 4)

struct StageRegs {
    float4 rA[2];
    float4 rB[4];
};

__device__ __forceinline__ void stage_ldg(StageRegs& R, const float* __restrict__ A,
                                          const float* __restrict__ BT,
                                          int m0, int kb, int t) {
#pragma unroll
    for (int i = 0; i < 2; i++) {
        int f = t + 512 * i;                 // 0..1023
        int row = f >> 3, j = f & 7;
        R.rA[i] = *(const float4*)(A + (size_t)(m0 + row) * HIDDEN + kb * 32 + j * 4);
    }
#pragma unroll
    for (int i = 0; i < 4; i++) {
        int f = t + 512 * i;                 // 0..2047
        int n = f >> 3, j = f & 7;
        R.rB[i] = *(const float4*)(BT + (size_t)n * HIDDEN + kb * 32 + j * 4);
    }
}

__device__ __forceinline__ void stage_sts(const StageRegs& R, float* __restrict__ buf,
                                          int t) {
    uint32_t* bufA = (uint32_t*)buf;          // 4096 words
    uint32_t* bufB = (uint32_t*)(buf + 4096); // 8192 words
#pragma unroll
    for (int i = 0; i < 2; i++) {
        int f = t + 512 * i;
        int row = f >> 3, j = f & 7;
        int mt = row >> 4, mr = row & 15;
        int gg = mr & 7, half = mr >> 3;
        float v[4] = {R.rA[i].x, R.rA[i].y, R.rA[i].z, R.rA[i].w};
#pragma unroll
        for (int e = 0; e < 4; e++) {
            int kk = j * 4 + e;
            int ks = kk >> 3, q = kk & 3, h2 = (kk >> 2) & 1;
            int reg = half + 2 * h2;
            bufA[((mt * 4 + ks) * 32 + gg * 4 + q) * 4 + reg] = cvt_tf32(v[e]);
        }
    }
#pragma unroll
    for (int i = 0; i < 4; i++) {
        int f = t + 512 * i;
        int n = f >> 3, j = f & 7;
        int nt = n >> 3, nr = n & 7;
        float v[4] = {R.rB[i].x, R.rB[i].y, R.rB[i].z, R.rB[i].w};
#pragma unroll
        for (int e = 0; e < 4; e++) {
            int kk = j * 4 + e;
            int ks = kk >> 3, reg = (kk >> 2) & 1;
            int laned = nr * 4 + (kk & 3);
            bufB[((nt * 4 + ks) * 32 + laned) * 2 + reg] = cvt_tf32(v[e]);
        }
    }
}

__global__ void __launch_bounds__(512, 1) k_gemm_mma(
    const float* __restrict__ A, const float* __restrict__ BT,
    float* __restrict__ C, const float* __restrict__ bias)
{
    extern __shared__ float sm[];
    const int t = threadIdx.x;
    const int lane = t & 31, wid = t >> 5;
    const int wm = wid & 3, wn = wid >> 2;
    const int m0 = blockIdx.x * 128;
    const int g = lane >> 2, tig = lane & 3;

    float acc[2][8][4];
#pragma unroll
    for (int i = 0; i < 2; i++)
#pragma unroll
        for (int j = 0; j < 8; j++)
#pragma unroll
            for (int k = 0; k < 4; k++) acc[i][j][k] = 0.f;

    StageRegs R;
    stage_ldg(R, A, BT, m0, 0, t);
    stage_sts(R, sm, t);
    __syncthreads();

#pragma unroll 1
    for (int kb = 0; kb < 8; kb++) {
        const float* buf = sm + (kb & 1) * STG_F;
        const uint32_t* bufA = (const uint32_t*)buf;
        const uint32_t* bufB = (const uint32_t*)(buf + 4096);
        if (kb < 7) stage_ldg(R, A, BT, m0, kb + 1, t);
#pragma unroll
        for (int ks = 0; ks < 4; ks++) {
            uint32_t afr[2][4];
#pragma unroll
            for (int mi = 0; mi < 2; mi++) {
                int mt = wm * 2 + mi;
                const uint4 v = *(const uint4*)&bufA[((mt * 4 + ks) * 32 + lane) * 4];
                afr[mi][0] = v.x; afr[mi][1] = v.y; afr[mi][2] = v.z; afr[mi][3] = v.w;
            }
#pragma unroll
            for (int nt8 = 0; nt8 < 8; nt8++) {
                int nt = wn * 8 + nt8;
                const uint2 b = *(const uint2*)&bufB[((nt * 4 + ks) * 32 + lane) * 2];
                mma_tf32(acc[0][nt8], afr[0], b.x, b.y);
                mma_tf32(acc[1][nt8], afr[1], b.x, b.y);
            }
        }
        if (kb < 7) {
            stage_sts(R, sm + ((kb + 1) & 1) * STG_F, t);
            __syncthreads();
        }
    }

    // epilogue
#pragma unroll
    for (int mi = 0; mi < 2; mi++) {
        int row = m0 + wm * 32 + mi * 16 + g;
#pragma unroll
        for (int nt8 = 0; nt8 < 8; nt8++) {
            int col = wn * 64 + nt8 * 8 + tig * 2;
            float b0 = 0.f, b1 = 0.f;
            if (bias) { b0 = __ldg(bias + col); b1 = __ldg(bias + col + 1); }
            float2 v0 = make_float2(acc[mi][nt8][0] + b0, acc[mi][nt8][1] + b1);
            float2 v1 = make_float2(acc[mi][nt8][2] + b0, acc[mi][nt8][3] + b1);
            *(float2*)(C + (size_t)row * HIDDEN + col) = v0;
            *(float2*)(C + (size_t)(row + 8) * HIDDEN + col) = v1;
        }
    }
}

// ---------------- CSR build ----------------
__global__ void k_init_deg() {
    int i = blockIdx.x * blockDim.x + threadIdx.x;
    if (i < N_NODES) g_deg[i] = 1;
}
__global__ void k_count_deg(const int* __restrict__ dst, int E) {
    int e = blockIdx.x * blockDim.x + threadIdx.x;
    if (e < E) atomicAdd(&g_deg[dst[e]], 1);
}
__global__ void k_scan() {
    __shared__ int sh[1024];
    int t = threadIdx.x;
    int base = t * 64;
    int s = 0;
    for (int j = 0; j < 64; j++) s += g_deg[base + j];
    sh[t] = s;
    __syncthreads();
    for (int d = 1; d < 1024; d <<= 1) {
        int v = (t >= d) ? sh[t - d] : 0;
        __syncthreads();
        sh[t] += v;
        __syncthreads();
    }
    int run = sh[t] - s;
    for (int j = 0; j < 64; j++) {
        g_off[base + j] = run;
        run += g_deg[base + j];
    }
    if (t == 1023) g_off[N_NODES] = run;
}
__global__ void k_init_cur() {
    int i = blockIdx.x * blockDim.x + threadIdx.x;
    if (i < N_NODES) g_cur[i] = g_off[i];
}
__global__ void k_fill(const int* __restrict__ src, const int* __restrict__ dst, int E) {
    int e = blockIdx.x * blockDim.x + threadIdx.x;
    if (e < E) {
        int pos = atomicAdd(&g_cur[dst[e]], 1);
        g_csr[pos] = src[e];
    }
}
__global__ void k_selfloop() {
    int i = blockIdx.x * blockDim.x + threadIdx.x;
    if (i < N_NODES) g_csr[g_off[i + 1] - 1] = i;
}

// ---------------- embedding gather ----------------
__global__ void k_embed(const int* __restrict__ nodes, const float* __restrict__ emb) {
    int idx = blockIdx.x * blockDim.x + threadIdx.x;
    if (idx < N_NODES * HIDDEN) {
        int n = idx >> 8;
        int c = idx & 255;
        g_x[idx] = emb[(size_t)nodes[n] * HIDDEN + c];
    }
}

// ---------------- scalar GEMM (output projection only) ----------------
#define BM 64
#define BN 64
#define BK 16
__global__ void k_gemm(const float* __restrict__ A, const float* __restrict__ B,
                       const float* __restrict__ bias, float* __restrict__ C,
                       int M, int N, int K) {
    __shared__ float As[BM][BK];
    __shared__ float Bs[BK][BN + 1];
    int tid = threadIdx.y * 16 + threadIdx.x;
    int m0 = blockIdx.y * BM, n0 = blockIdx.x * BN;
    float acc[4][4] = {};
    for (int k0 = 0; k0 < K; k0 += BK) {
#pragma unroll
        for (int r = 0; r < 4; r++) {
            int e = tid + r * 256;
            int m = e / BK, k = e % BK;
            As[m][k] = (m0 + m < M) ? A[(size_t)(m0 + m) * K + k0 + k] : 0.f;
        }
#pragma unroll
        for (int r = 0; r < 4; r++) {
            int e = tid + r * 256;
            int k = e / BN, n = e % BN;
            Bs[k][n] = (n0 + n < N) ? B[(size_t)(k0 + k) * N + n0 + n] : 0.f;
        }
        __syncthreads();
#pragma unroll
        for (int kk = 0; kk < BK; kk++) {
            float ra[4], rb[4];
#pragma unroll
            for (int i = 0; i < 4; i++) ra[i] = As[threadIdx.y * 4 + i][kk];
#pragma unroll
            for (int j = 0; j < 4; j++) rb[j] = Bs[kk][threadIdx.x * 4 + j];
#pragma unroll
            for (int i = 0; i < 4; i++)
#pragma unroll
                for (int j = 0; j < 4; j++) acc[i][j] += ra[i] * rb[j];
        }
        __syncthreads();
    }
#pragma unroll
    for (int i = 0; i < 4; i++) {
        int m = m0 + threadIdx.y * 4 + i;
        if (m >= M) continue;
#pragma unroll
        for (int j = 0; j < 4; j++) {
            int n = n0 + threadIdx.x * 4 + j;
            if (n >= N) continue;
            float v = acc[i][j];
            if (bias) v += bias[n];
            C[(size_t)m * N + n] = v;
        }
    }
}

// ---------------- attention scalar dots ----------------
__global__ void k_dots(const float* __restrict__ h, const float* __restrict__ a_s,
                       const float* __restrict__ a_d) {
    int w = (blockIdx.x * blockDim.x + threadIdx.x) >> 5;
    int lane = threadIdx.x & 31;
    if (w >= N_NODES) return;
    const float* row = h + (size_t)w * HIDDEN;
    float s = 0.f, d = 0.f;
#pragma unroll
    for (int j = 0; j < 8; j++) {
        int c = lane + 32 * j;
        float v = row[c];
        s += v * a_s[c];
        d += v * a_d[c];
    }
#pragma unroll
    for (int o = 16; o; o >>= 1) {
        s += __shfl_xor_sync(0xffffffffu, s, o);
        d += __shfl_xor_sync(0xffffffffu, d, o);
    }
    if (lane == 0) { g_es[w] = s; g_ed[w] = d; }
}

__device__ __forceinline__ float leaky(float v) {
    return v > 0.f ? v : NEG_SLOPE * v;
}

// ---------------- GAT aggregation: one warp per dst node ----------------
__global__ void k_agg(const float* __restrict__ h, const float* __restrict__ bg,
                      float* __restrict__ out) {
    int w = (blockIdx.x * blockDim.x + threadIdx.x) >> 5;
    int lane = threadIdx.x & 31;
    if (w >= N_NODES) return;
    int b0 = g_off[w], b1 = g_off[w + 1];
    float edv = g_ed[w];
    float m = -1e30f;
    for (int e = b0 + lane; e < b1; e += 32)
        m = fmaxf(m, leaky(g_es[g_csr[e]] + edv));
#pragma unroll
    for (int o = 16; o; o >>= 1) m = fmaxf(m, __shfl_xor_sync(0xffffffffu, m, o));
    float s = 0.f;
    for (int e = b0 + lane; e < b1; e += 32)
        s += __expf(leaky(g_es[g_csr[e]] + edv) - m);
#pragma unroll
    for (int o = 16; o; o >>= 1) s += __shfl_xor_sync(0xffffffffu, s, o);
    float inv = 1.f / (s + EPS_SM);
    float acc[8] = {};
    for (int e = b0; e < b1; e++) {
        int src = g_csr[e];
        float a = __expf(leaky(g_es[src] + edv) - m) * inv;
        const float* hr = h + (size_t)src * HIDDEN;
#pragma unroll
        for (int j = 0; j < 8; j++) acc[j] += a * hr[lane + 32 * j];
    }
#pragma unroll
    for (int j = 0; j < 8; j++) {
        int c = lane + 32 * j;
        out[(size_t)w * HIDDEN + c] = fmaxf(acc[j] + bg[c], 0.f);
    }
}

// ---------------- mean pool ----------------
__global__ void k_pool_zero() {
    int i = blockIdx.x * blockDim.x + threadIdx.x;
    if (i < NUM_GRAPHS * HIDDEN) g_pool[i] = 0.f;
    if (i < NUM_GRAPHS) g_gcnt[i] = 0;
}
__global__ void k_counts(const int* __restrict__ batch) {
    int i = blockIdx.x * blockDim.x + threadIdx.x;
    if (i < N_NODES) atomicAdd(&g_gcnt[batch[i]], 1);
}
__global__ void k_pool(const float* __restrict__ x, const int* __restrict__ batch) {
    __shared__ int shb[256];
    int c = threadIdx.x;
    int n0 = blockIdx.x * 256;
    shb[c] = batch[n0 + c];
    __syncthreads();
    float acc = 0.f;
    int cg = shb[0];
    for (int n = 0; n < 256; n++) {
        int g = shb[n];
        if (g != cg) {
            atomicAdd(&g_pool[cg * HIDDEN + c], acc);
            acc = 0.f;
            cg = g;
        }
        acc += x[(size_t)(n0 + n) * HIDDEN + c];
    }
    atomicAdd(&g_pool[cg * HIDDEN + c], acc);
}
__global__ void k_mean() {
    int i = blockIdx.x * blockDim.x + threadIdx.x;
    if (i < NUM_GRAPHS * HIDDEN) {
        float cnt = (float)g_gcnt[i >> 8];
        g_pool[i] /= fmaxf(cnt, 1.f);
    }
}

// ---------------- launch ----------------
extern "C" void kernel_launch(void* const* d_in, const int* in_sizes, int n_in,
                              void* d_out, int out_size) {
    const int*   nodes = (const int*)d_in[0];
    const int*   eidx  = (const int*)d_in[1];
    const int*   batch = (const int*)d_in[2];
    const float* emb   = (const float*)d_in[3];
    const float* Wg    = (const float*)d_in[4];
    const float* a_src = (const float*)d_in[5];
    const float* a_dst = (const float*)d_in[6];
    const float* bg    = (const float*)d_in[7];
    const float* Wl    = (const float*)d_in[8];
    const float* bl    = (const float*)d_in[9];
    const float* Wout  = (const float*)d_in[10];
    const float* bout  = (const float*)d_in[11];

    const int E = in_sizes[1] / 2;
    const int* src = eidx;
    const int* dst = eidx + E;

    float *dx, *dh, *dt, *dpool, *dWT;
    cudaGetSymbolAddress((void**)&dx, g_x);
    cudaGetSymbolAddress((void**)&dh, g_h);
    cudaGetSymbolAddress((void**)&dt, g_t);
    cudaGetSymbolAddress((void**)&dpool, g_pool);
    cudaGetSymbolAddress((void**)&dWT, g_WT);

    cudaFuncSetAttribute(k_gemm_mma, cudaFuncAttributeMaxDynamicSharedMemorySize,
                         SMEM_MMA);

    // CSR build
    k_init_deg<<<N_NODES / 256, 256>>>();
    k_count_deg<<<(E + 255) / 256, 256>>>(dst, E);
    k_scan<<<1, 1024>>>();
    k_init_cur<<<N_NODES / 256, 256>>>();
    k_fill<<<(E + 255) / 256, 256>>>(src, dst, E);
    k_selfloop<<<N_NODES / 256, 256>>>();

    // weight transposes + embedding
    k_transpose<<<(2 * LAYERS * HIDDEN * HIDDEN) / 256, 256>>>(Wg, Wl);
    k_embed<<<(N_NODES * HIDDEN) / 256, 256>>>(nodes, emb);

    const int warp_blocks = (N_NODES * 32) / 256;
    const int GRID = N_NODES / 128;

    for (int l = 0; l < LAYERS; l++) {
        const float* WgT = dWT + (size_t)l * HIDDEN * HIDDEN;
        const float* WlT = dWT + (size_t)(LAYERS + l) * HIDDEN * HIDDEN;
        // h = x @ Wg[l]
        k_gemm_mma<<<GRID, 512, SMEM_MMA>>>(dx, WgT, dh, nullptr);
        // es/ed dots
        k_dots<<<warp_blocks, 256>>>(dh, a_src + l * HIDDEN, a_dst + l * HIDDEN);
        // segment softmax + aggregation (+bg, relu)
        k_agg<<<warp_blocks, 256>>>(dh, bg + l * HIDDEN, dt);
        // x = t @ Wl[l] + bl[l]
        k_gemm_mma<<<GRID, 512, SMEM_MMA>>>(dt, WlT, dx, bl + l * HIDDEN);
    }

    // mean pool
    k_pool_zero<<<(NUM_GRAPHS * HIDDEN + 255) / 256, 256>>>();
    k_counts<<<N_NODES / 256, 256>>>(batch);
    k_pool<<<N_NODES / 256, 256>>>(dx, batch);
    k_mean<<<(NUM_GRAPHS * HIDDEN + 255) / 256, 256>>>();

    // out[64, 50000] = pooled @ Wout + bout
    dim3 blk(16, 16);
    dim3 grd_out((VOCAB + BN - 1) / BN, (NUM_GRAPHS + BM - 1) / BM);
    k_gemm<<<grd_out, blk>>>(dpool, Wout, bout, (float*)d_out,
                             NUM_GRAPHS, VOCAB, HIDDEN);
}

// round 4
// speedup vs baseline: 2.5746x; 1.3085x over previous
#include <cuda_runtime.h>
#include <cuda_fp16.h>
#include <cstdint>
#include <math.h>

#define N_NODES   65536
#define HIDDEN    256
#define NUM_GRAPHS 64
#define VOCAB     50000
#define LAYERS    3
#define MAX_E     1114112
#define NEG_SLOPE 0.2f
#define EPS_SM    1e-16f

// ---------------- scratch ----------------
__device__ __half g_x[N_NODES * HIDDEN];
__device__ __half g_h[N_NODES * HIDDEN];
__device__ __half g_t[N_NODES * HIDDEN];
__device__ __half g_WT[2 * LAYERS * HIDDEN * HIDDEN];  // [0..2]=Wg^T, [3..5]=Wl^T
__device__ float g_es[N_NODES];
__device__ float g_ed[N_NODES];
__device__ int   g_deg[N_NODES];
__device__ int   g_off[N_NODES + 1];
__device__ int   g_cur[N_NODES];
__device__ int   g_csr[MAX_E];
__device__ float g_pool[NUM_GRAPHS * HIDDEN];
__device__ int   g_gcnt[NUM_GRAPHS];

__device__ __forceinline__ void mma_f16(float* c, const uint32_t* a,
                                        uint32_t b0, uint32_t b1) {
    asm volatile(
        "mma.sync.aligned.m16n8k16.row.col.f32.f16.f16.f32 "
        "{%0,%1,%2,%3}, {%4,%5,%6,%7}, {%8,%9}, {%0,%1,%2,%3};\n"
        : "+f"(c[0]), "+f"(c[1]), "+f"(c[2]), "+f"(c[3])
        : "r"(a[0]), "r"(a[1]), "r"(a[2]), "r"(a[3]), "r"(b0), "r"(b1));
}

// ---------------- weight transpose: WT[n*256+k] = half(W[k*256+n]) ----------------
__global__ void k_transpose(const float* __restrict__ Wg, const float* __restrict__ Wl) {
    int i = blockIdx.x * 256 + threadIdx.x;
    int which = i / (LAYERS * HIDDEN * HIDDEN);
    int rem = i % (LAYERS * HIDDEN * HIDDEN);
    int l = rem / (HIDDEN * HIDDEN);
    int nk = rem % (HIDDEN * HIDDEN);
    int n = nk >> 8, k = nk & 255;
    const float* W = which ? Wl : Wg;
    g_WT[i] = __float2half(W[l * HIDDEN * HIDDEN + k * HIDDEN + n]);
}

// ============ fp16 mma GEMM: C[65536,256](half) = A(half) @ WT^T(half) ============
// CTA 128x256, BK=32, 512 threads = 16 warps (4m x 4n), warp tile 32x64.
// Stage (b32 words): A 2048 + B 4096 = 6144 words = 24KB; x2 stages + 1KB reduction.
#define STG_W 6144
#define RED_W 12288
#define SMEM_MMA (RED_W * 4 + 1024)

struct StageRegs { uint4 a, b0, b1; };

__device__ __forceinline__ void stage_ldg(StageRegs& R, const __half* __restrict__ A,
                                          const __half* __restrict__ BT,
                                          int m0, int kb, int t) {
    {
        int row = t >> 2, j = t & 3;
        R.a = *(const uint4*)(A + (size_t)(m0 + row) * HIDDEN + kb * 32 + j * 8);
    }
#pragma unroll
    for (int i = 0; i < 2; i++) {
        int f = t + 512 * i;
        int n = f >> 2, j = f & 3;
        uint4 v = *(const uint4*)(BT + (size_t)n * HIDDEN + kb * 32 + j * 8);
        if (i == 0) R.b0 = v; else R.b1 = v;
    }
}

__device__ __forceinline__ void stage_sts(const StageRegs& R, uint32_t* __restrict__ buf,
                                          int t) {
    {
        int row = t >> 2, j = t & 3;
        int mt = row >> 4, mr = row & 15, g = mr & 7;
        int ks = j >> 1, reg = (mr >> 3) + 2 * (j & 1);
        uint32_t wb = ((mt * 2 + ks) * 32 + g * 4) * 4 + reg;
        buf[wb] = R.a.x; buf[wb + 4] = R.a.y; buf[wb + 8] = R.a.z; buf[wb + 12] = R.a.w;
    }
#pragma unroll
    for (int i = 0; i < 2; i++) {
        int f = t + 512 * i;
        int n = f >> 2, j = f & 3;
        int nt = n >> 3, g = n & 7;
        int ks = j >> 1, reg = j & 1;
        uint4 v = (i == 0) ? R.b0 : R.b1;
        uint32_t wb = 2048 + ((nt * 2 + ks) * 32 + g * 4) * 2 + reg;
        buf[wb] = v.x; buf[wb + 2] = v.y; buf[wb + 4] = v.z; buf[wb + 6] = v.w;
    }
}

__global__ void __launch_bounds__(512, 1) k_gemm_mma(
    const __half* __restrict__ A, const __half* __restrict__ BT,
    __half* __restrict__ C, const float* __restrict__ bias,
    const float* __restrict__ avS, const float* __restrict__ avD,
    float* __restrict__ es, float* __restrict__ ed)
{
    extern __shared__ uint32_t smw[];
    float* red = (float*)(smw + RED_W);
    const int t = threadIdx.x;
    const int lane = t & 31, wid = t >> 5;
    const int wm = wid & 3, wn = wid >> 2;
    const int m0 = blockIdx.x * 128;
    const int g = lane >> 2, tig = lane & 3;

    if (t < 256) red[t] = 0.f;

    float acc[2][8][4];
#pragma unroll
    for (int i = 0; i < 2; i++)
#pragma unroll
        for (int j = 0; j < 8; j++)
#pragma unroll
            for (int k = 0; k < 4; k++) acc[i][j][k] = 0.f;

    StageRegs R;
    stage_ldg(R, A, BT, m0, 0, t);
    stage_sts(R, smw, t);
    __syncthreads();

#pragma unroll 1
    for (int kb = 0; kb < 8; kb++) {
        const uint32_t* buf = smw + (kb & 1) * STG_W;
        if (kb < 7) stage_ldg(R, A, BT, m0, kb + 1, t);
#pragma unroll
        for (int ks = 0; ks < 2; ks++) {
            uint4 av[2];
#pragma unroll
            for (int mi = 0; mi < 2; mi++) {
                int mt = wm * 2 + mi;
                av[mi] = *(const uint4*)&buf[((mt * 2 + ks) * 32 + lane) * 4];
            }
#pragma unroll
            for (int nt8 = 0; nt8 < 8; nt8++) {
                int nt = wn * 8 + nt8;
                uint2 bv = *(const uint2*)&buf[2048 + ((nt * 2 + ks) * 32 + lane) * 2];
                mma_f16(acc[0][nt8], (const uint32_t*)&av[0], bv.x, bv.y);
                mma_f16(acc[1][nt8], (const uint32_t*)&av[1], bv.x, bv.y);
            }
        }
        if (kb < 7) {
            stage_sts(R, smw + ((kb + 1) & 1) * STG_W, t);
            __syncthreads();
        }
    }

    // ---------------- epilogue ----------------
    float esp[2][2] = {{0.f, 0.f}, {0.f, 0.f}};
    float edp[2][2] = {{0.f, 0.f}, {0.f, 0.f}};
#pragma unroll
    for (int mi = 0; mi < 2; mi++) {
        int row = m0 + wm * 32 + mi * 16 + g;
#pragma unroll
        for (int nt8 = 0; nt8 < 8; nt8++) {
            int col = wn * 64 + nt8 * 8 + tig * 2;
            float a0 = acc[mi][nt8][0], a1 = acc[mi][nt8][1];
            float a2 = acc[mi][nt8][2], a3 = acc[mi][nt8][3];
            if (bias) {
                float b0 = __ldg(bias + col), b1 = __ldg(bias + col + 1);
                a0 += b0; a1 += b1; a2 += b0; a3 += b1;
            }
            *(__half2*)(C + (size_t)row * HIDDEN + col) = __floats2half2_rn(a0, a1);
            *(__half2*)(C + (size_t)(row + 8) * HIDDEN + col) = __floats2half2_rn(a2, a3);
            if (avS) {
                float s0 = __ldg(avS + col), s1 = __ldg(avS + col + 1);
                float d0 = __ldg(avD + col), d1 = __ldg(avD + col + 1);
                esp[mi][0] += a0 * s0 + a1 * s1;
                esp[mi][1] += a2 * s0 + a3 * s1;
                edp[mi][0] += a0 * d0 + a1 * d1;
                edp[mi][1] += a2 * d0 + a3 * d1;
            }
        }
    }
    if (avS) {
#pragma unroll
        for (int o = 1; o <= 2; o <<= 1) {
#pragma unroll
            for (int mi = 0; mi < 2; mi++)
#pragma unroll
                for (int hv = 0; hv < 2; hv++) {
                    esp[mi][hv] += __shfl_xor_sync(0xffffffffu, esp[mi][hv], o);
                    edp[mi][hv] += __shfl_xor_sync(0xffffffffu, edp[mi][hv], o);
                }
        }
        if (tig == 0) {
#pragma unroll
            for (int mi = 0; mi < 2; mi++)
#pragma unroll
                for (int hv = 0; hv < 2; hv++) {
                    int rl = wm * 32 + mi * 16 + hv * 8 + g;
                    atomicAdd(&red[rl], esp[mi][hv]);
                    atomicAdd(&red[128 + rl], edp[mi][hv]);
                }
        }
        __syncthreads();
        if (t < 128) {
            es[m0 + t] = red[t];
            ed[m0 + t] = red[128 + t];
        }
    }
}

// ---------------- CSR build ----------------
__global__ void k_init_deg() {
    int i = blockIdx.x * blockDim.x + threadIdx.x;
    if (i < N_NODES) g_deg[i] = 1;
}
__global__ void k_count_deg(const int* __restrict__ dst, int E) {
    int e = blockIdx.x * blockDim.x + threadIdx.x;
    if (e < E) atomicAdd(&g_deg[dst[e]], 1);
}
__global__ void k_scan() {
    __shared__ int sh[1024];
    int t = threadIdx.x;
    int base = t * 64;
    int s = 0;
    for (int j = 0; j < 64; j++) s += g_deg[base + j];
    sh[t] = s;
    __syncthreads();
    for (int d = 1; d < 1024; d <<= 1) {
        int v = (t >= d) ? sh[t - d] : 0;
        __syncthreads();
        sh[t] += v;
        __syncthreads();
    }
    int run = sh[t] - s;
    for (int j = 0; j < 64; j++) {
        g_off[base + j] = run;
        run += g_deg[base + j];
    }
    if (t == 1023) g_off[N_NODES] = run;
}
__global__ void k_init_cur() {
    int i = blockIdx.x * blockDim.x + threadIdx.x;
    if (i < N_NODES) g_cur[i] = g_off[i];
}
__global__ void k_fill(const int* __restrict__ src, const int* __restrict__ dst, int E) {
    int e = blockIdx.x * blockDim.x + threadIdx.x;
    if (e < E) {
        int pos = atomicAdd(&g_cur[dst[e]], 1);
        g_csr[pos] = src[e];
    }
}
__global__ void k_selfloop() {
    int i = blockIdx.x * blockDim.x + threadIdx.x;
    if (i < N_NODES) g_csr[g_off[i + 1] - 1] = i;
}

// ---------------- embedding gather (writes half) ----------------
__global__ void k_embed(const int* __restrict__ nodes, const float* __restrict__ emb) {
    int idx = blockIdx.x * blockDim.x + threadIdx.x;
    if (idx < N_NODES * HIDDEN) {
        int n = idx >> 8;
        int c = idx & 255;
        g_x[idx] = __float2half(emb[(size_t)nodes[n] * HIDDEN + c]);
    }
}

// ---------------- scalar GEMM (output projection only) ----------------
#define BM 64
#define BN 64
#define BK 16
__global__ void k_gemm(const float* __restrict__ A, const float* __restrict__ B,
                       const float* __restrict__ bias, float* __restrict__ C,
                       int M, int N, int K) {
    __shared__ float As[BM][BK];
    __shared__ float Bs[BK][BN + 1];
    int tid = threadIdx.y * 16 + threadIdx.x;
    int m0 = blockIdx.y * BM, n0 = blockIdx.x * BN;
    float acc[4][4] = {};
    for (int k0 = 0; k0 < K; k0 += BK) {
#pragma unroll
        for (int r = 0; r < 4; r++) {
            int e = tid + r * 256;
            int m = e / BK, k = e % BK;
            As[m][k] = (m0 + m < M) ? A[(size_t)(m0 + m) * K + k0 + k] : 0.f;
        }
#pragma unroll
        for (int r = 0; r < 4; r++) {
            int e = tid + r * 256;
            int k = e / BN, n = e % BN;
            Bs[k][n] = (n0 + n < N) ? B[(size_t)(k0 + k) * N + n0 + n] : 0.f;
        }
        __syncthreads();
#pragma unroll
        for (int kk = 0; kk < BK; kk++) {
            float ra[4], rb[4];
#pragma unroll
            for (int i = 0; i < 4; i++) ra[i] = As[threadIdx.y * 4 + i][kk];
#pragma unroll
            for (int j = 0; j < 4; j++) rb[j] = Bs[kk][threadIdx.x * 4 + j];
#pragma unroll
            for (int i = 0; i < 4; i++)
#pragma unroll
                for (int j = 0; j < 4; j++) acc[i][j] += ra[i] * rb[j];
        }
        __syncthreads();
    }
#pragma unroll
    for (int i = 0; i < 4; i++) {
        int m = m0 + threadIdx.y * 4 + i;
        if (m >= M) continue;
#pragma unroll
        for (int j = 0; j < 4; j++) {
            int n = n0 + threadIdx.x * 4 + j;
            if (n >= N) continue;
            float v = acc[i][j];
            if (bias) v += bias[n];
            C[(size_t)m * N + n] = v;
        }
    }
}

__device__ __forceinline__ float leaky(float v) {
    return v > 0.f ? v : NEG_SLOPE * v;
}

// ---------------- GAT aggregation: one warp per dst node (half I/O) ----------------
__global__ void k_agg(const __half* __restrict__ h, const float* __restrict__ bg,
                      __half* __restrict__ out) {
    int w = (blockIdx.x * blockDim.x + threadIdx.x) >> 5;
    int lane = threadIdx.x & 31;
    if (w >= N_NODES) return;
    int b0 = g_off[w], b1 = g_off[w + 1];
    float edv = g_ed[w];
    float m = -1e30f;
    for (int e = b0 + lane; e < b1; e += 32)
        m = fmaxf(m, leaky(g_es[g_csr[e]] + edv));
#pragma unroll
    for (int o = 16; o; o >>= 1) m = fmaxf(m, __shfl_xor_sync(0xffffffffu, m, o));
    float s = 0.f;
    for (int e = b0 + lane; e < b1; e += 32)
        s += __expf(leaky(g_es[g_csr[e]] + edv) - m);
#pragma unroll
    for (int o = 16; o; o >>= 1) s += __shfl_xor_sync(0xffffffffu, s, o);
    float inv = 1.f / (s + EPS_SM);
    float2 acc[4] = {};
    for (int e = b0; e < b1; e++) {
        int src = g_csr[e];
        float a = __expf(leaky(g_es[src] + edv) - m) * inv;
        const __half2* hr = (const __half2*)(h + (size_t)src * HIDDEN);
#pragma unroll
        for (int j = 0; j < 4; j++) {
            float2 f = __half22float2(hr[lane + 32 * j]);
            acc[j].x += a * f.x;
            acc[j].y += a * f.y;
        }
    }
    __half2* op = (__half2*)(out + (size_t)w * HIDDEN);
#pragma unroll
    for (int j = 0; j < 4; j++) {
        int c2 = lane + 32 * j;
        float2 b2 = ((const float2*)bg)[c2];
        op[c2] = __floats2half2_rn(fmaxf(acc[j].x + b2.x, 0.f),
                                   fmaxf(acc[j].y + b2.y, 0.f));
    }
}

// ---------------- mean pool (half input) ----------------
__global__ void k_pool_zero() {
    int i = blockIdx.x * blockDim.x + threadIdx.x;
    if (i < NUM_GRAPHS * HIDDEN) g_pool[i] = 0.f;
    if (i < NUM_GRAPHS) g_gcnt[i] = 0;
}
__global__ void k_counts(const int* __restrict__ batch) {
    int i = blockIdx.x * blockDim.x + threadIdx.x;
    if (i < N_NODES) atomicAdd(&g_gcnt[batch[i]], 1);
}
__global__ void k_pool(const __half* __restrict__ x, const int* __restrict__ batch) {
    __shared__ int shb[256];
    int c = threadIdx.x;
    int n0 = blockIdx.x * 256;
    shb[c] = batch[n0 + c];
    __syncthreads();
    float acc = 0.f;
    int cg = shb[0];
    for (int n = 0; n < 256; n++) {
        int g = shb[n];
        if (g != cg) {
            atomicAdd(&g_pool[cg * HIDDEN + c], acc);
            acc = 0.f;
            cg = g;
        }
        acc += __half2float(x[(size_t)(n0 + n) * HIDDEN + c]);
    }
    atomicAdd(&g_pool[cg * HIDDEN + c], acc);
}
__global__ void k_mean() {
    int i = blockIdx.x * blockDim.x + threadIdx.x;
    if (i < NUM_GRAPHS * HIDDEN) {
        float cnt = (float)g_gcnt[i >> 8];
        g_pool[i] /= fmaxf(cnt, 1.f);
    }
}

// ---------------- launch ----------------
extern "C" void kernel_launch(void* const* d_in, const int* in_sizes, int n_in,
                              void* d_out, int out_size) {
    const int*   nodes = (const int*)d_in[0];
    const int*   eidx  = (const int*)d_in[1];
    const int*   batch = (const int*)d_in[2];
    const float* emb   = (const float*)d_in[3];
    const float* Wg    = (const float*)d_in[4];
    const float* a_src = (const float*)d_in[5];
    const float* a_dst = (const float*)d_in[6];
    const float* bg    = (const float*)d_in[7];
    const float* Wl    = (const float*)d_in[8];
    const float* bl    = (const float*)d_in[9];
    const float* Wout  = (const float*)d_in[10];
    const float* bout  = (const float*)d_in[11];

    const int E = in_sizes[1] / 2;
    const int* src = eidx;
    const int* dst = eidx + E;

    __half *dx, *dh, *dt, *dWT;
    float *dpool, *des, *ded;
    cudaGetSymbolAddress((void**)&dx, g_x);
    cudaGetSymbolAddress((void**)&dh, g_h);
    cudaGetSymbolAddress((void**)&dt, g_t);
    cudaGetSymbolAddress((void**)&dpool, g_pool);
    cudaGetSymbolAddress((void**)&dWT, g_WT);
    cudaGetSymbolAddress((void**)&des, g_es);
    cudaGetSymbolAddress((void**)&ded, g_ed);

    cudaFuncSetAttribute(k_gemm_mma, cudaFuncAttributeMaxDynamicSharedMemorySize,
                         SMEM_MMA);

    // CSR build
    k_init_deg<<<N_NODES / 256, 256>>>();
    k_count_deg<<<(E + 255) / 256, 256>>>(dst, E);
    k_scan<<<1, 1024>>>();
    k_init_cur<<<N_NODES / 256, 256>>>();
    k_fill<<<(E + 255) / 256, 256>>>(src, dst, E);
    k_selfloop<<<N_NODES / 256, 256>>>();

    // weight transposes + embedding
    k_transpose<<<(2 * LAYERS * HIDDEN * HIDDEN) / 256, 256>>>(Wg, Wl);
    k_embed<<<(N_NODES * HIDDEN) / 256, 256>>>(nodes, emb);

    const int warp_blocks = (N_NODES * 32) / 256;
    const int GRID = N_NODES / 128;

    for (int l = 0; l < LAYERS; l++) {
        const __half* WgT = dWT + (size_t)l * HIDDEN * HIDDEN;
        const __half* WlT = dWT + (size_t)(LAYERS + l) * HIDDEN * HIDDEN;
        // h = x @ Wg[l]  (+ fused es/ed dot products)
        k_gemm_mma<<<GRID, 512, SMEM_MMA>>>(dx, WgT, dh, nullptr,
                                            a_src + l * HIDDEN, a_dst + l * HIDDEN,
                                            des, ded);
        // segment softmax + aggregation (+bg, relu)
        k_agg<<<warp_blocks, 256>>>(dh, bg + l * HIDDEN, dt);
        // x = t @ Wl[l] + bl[l]
        k_gemm_mma<<<GRID, 512, SMEM_MMA>>>(dt, WlT, dx, bl + l * HIDDEN,
                                            nullptr, nullptr, nullptr, nullptr);
    }

    // mean pool
    k_pool_zero<<<(NUM_GRAPHS * HIDDEN + 255) / 256, 256>>>();
    k_counts<<<N_NODES / 256, 256>>>(batch);
    k_pool<<<N_NODES / 256, 256>>>(dx, batch);
    k_mean<<<(NUM_GRAPHS * HIDDEN + 255) / 256, 256>>>();

    // out[64, 50000] = pooled @ Wout + bout
    dim3 blk(16, 16);
    dim3 grd_out((VOCAB + BN - 1) / BN, (NUM_GRAPHS + BM - 1) / BM);
    k_gemm<<<grd_out, blk>>>(dpool, Wout, bout, (float*)d_out,
                             NUM_GRAPHS, VOCAB, HIDDEN);
}

// round 5
// speedup vs baseline: 2.8374x; 1.1021x over previous
#include <cuda_runtime.h>
#include <cuda_fp16.h>
#include <cstdint>
#include <math.h>

#define N_NODES   65536
#define HIDDEN    256
#define NUM_GRAPHS 64
#define VOCAB     50000
#define LAYERS    3
#define MAX_E     1114112
#define NEG_SLOPE 0.2f
#define EPS_SM    1e-16f

// ---------------- scratch ----------------
__device__ __half g_x[N_NODES * HIDDEN];   // embed output
__device__ __half g_h[N_NODES * HIDDEN];   // h per layer
__device__ __half g_t[N_NODES * HIDDEN];   // agg output per layer
__device__ __half g_WT[LAYERS * HIDDEN * HIDDEN];   // transposed half weights (3 mats)
__device__ float g_Wc[2 * HIDDEN * HIDDEN];          // composed fp32 weights
__device__ float g_bc[2 * HIDDEN];                   // composed biases
__device__ float g_es[N_NODES];
__device__ float g_ed[N_NODES];
__device__ int   g_deg[N_NODES];
__device__ int   g_off[N_NODES + 1];
__device__ int   g_cur[N_NODES];
__device__ int   g_csr[MAX_E];
__device__ float g_pool[NUM_GRAPHS * HIDDEN];
__device__ float g_small[NUM_GRAPHS * HIDDEN];
__device__ int   g_gcnt[NUM_GRAPHS];

__device__ __forceinline__ void mma_f16(float* c, const uint32_t* a,
                                        uint32_t b0, uint32_t b1) {
    asm volatile(
        "mma.sync.aligned.m16n8k16.row.col.f32.f16.f16.f32 "
        "{%0,%1,%2,%3}, {%4,%5,%6,%7}, {%8,%9}, {%0,%1,%2,%3};\n"
        : "+f"(c[0]), "+f"(c[1]), "+f"(c[2]), "+f"(c[3])
        : "r"(a[0]), "r"(a[1]), "r"(a[2]), "r"(a[3]), "r"(b0), "r"(b1));
}

// ---------------- weight transposes ----------------
// slot 0: Wg[0]^T
__global__ void k_transpose0(const float* __restrict__ Wg) {
    int i = blockIdx.x * 256 + threadIdx.x;         // 0..65535
    int n = i >> 8, k = i & 255;
    g_WT[i] = __float2half(Wg[k * HIDDEN + n]);
}
// slots 1,2: composed Wc^T
__global__ void k_transpose_c() {
    int i = blockIdx.x * 256 + threadIdx.x;         // 0..131071
    int which = i >> 16;
    int nk = i & 65535;
    int n = nk >> 8, k = nk & 255;
    g_WT[(1 + which) * HIDDEN * HIDDEN + nk] =
        __float2half(g_Wc[which * HIDDEN * HIDDEN + k * HIDDEN + n]);
}
// composed biases: bc[l][n] = sum_k bl[l][k] * Wg[l+1][k*256+n]
__global__ void k_bias_c(const float* __restrict__ bl, const float* __restrict__ Wg) {
    int which = blockIdx.x;                          // 0..1
    int n = threadIdx.x;
    const float* b = bl + which * HIDDEN;
    const float* W = Wg + (which + 1) * HIDDEN * HIDDEN;
    float s = 0.f;
    for (int k = 0; k < HIDDEN; k++) s += b[k] * W[k * HIDDEN + n];
    g_bc[which * HIDDEN + n] = s;
}

// ============ fp16 mma GEMM: C[65536,256](half) = A(half) @ WT^T(half) ============
#define STG_W 6144
#define RED_W 12288
#define SMEM_MMA (RED_W * 4 + 1024)

struct StageRegs { uint4 a, b0, b1; };

__device__ __forceinline__ void stage_ldg(StageRegs& R, const __half* __restrict__ A,
                                          const __half* __restrict__ BT,
                                          int m0, int kb, int t) {
    {
        int row = t >> 2, j = t & 3;
        R.a = *(const uint4*)(A + (size_t)(m0 + row) * HIDDEN + kb * 32 + j * 8);
    }
#pragma unroll
    for (int i = 0; i < 2; i++) {
        int f = t + 512 * i;
        int n = f >> 2, j = f & 3;
        uint4 v = *(const uint4*)(BT + (size_t)n * HIDDEN + kb * 32 + j * 8);
        if (i == 0) R.b0 = v; else R.b1 = v;
    }
}

__device__ __forceinline__ void stage_sts(const StageRegs& R, uint32_t* __restrict__ buf,
                                          int t) {
    {
        int row = t >> 2, j = t & 3;
        int mt = row >> 4, mr = row & 15, g = mr & 7;
        int ks = j >> 1, reg = (mr >> 3) + 2 * (j & 1);
        uint32_t wb = ((mt * 2 + ks) * 32 + g * 4) * 4 + reg;
        buf[wb] = R.a.x; buf[wb + 4] = R.a.y; buf[wb + 8] = R.a.z; buf[wb + 12] = R.a.w;
    }
#pragma unroll
    for (int i = 0; i < 2; i++) {
        int f = t + 512 * i;
        int n = f >> 2, j = f & 3;
        int nt = n >> 3, g = n & 7;
        int ks = j >> 1, reg = j & 1;
        uint4 v = (i == 0) ? R.b0 : R.b1;
        uint32_t wb = 2048 + ((nt * 2 + ks) * 32 + g * 4) * 2 + reg;
        buf[wb] = v.x; buf[wb + 2] = v.y; buf[wb + 4] = v.z; buf[wb + 6] = v.w;
    }
}

__global__ void __launch_bounds__(512, 1) k_gemm_mma(
    const __half* __restrict__ A, const __half* __restrict__ BT,
    __half* __restrict__ C, const float* __restrict__ bias,
    const float* __restrict__ avS, const float* __restrict__ avD,
    float* __restrict__ es, float* __restrict__ ed)
{
    extern __shared__ uint32_t smw[];
    float* red = (float*)(smw + RED_W);
    const int t = threadIdx.x;
    const int lane = t & 31, wid = t >> 5;
    const int wm = wid & 3, wn = wid >> 2;
    const int m0 = blockIdx.x * 128;
    const int g = lane >> 2, tig = lane & 3;

    if (t < 256) red[t] = 0.f;

    float acc[2][8][4];
#pragma unroll
    for (int i = 0; i < 2; i++)
#pragma unroll
        for (int j = 0; j < 8; j++)
#pragma unroll
            for (int k = 0; k < 4; k++) acc[i][j][k] = 0.f;

    StageRegs R;
    stage_ldg(R, A, BT, m0, 0, t);
    stage_sts(R, smw, t);
    __syncthreads();

#pragma unroll 1
    for (int kb = 0; kb < 8; kb++) {
        const uint32_t* buf = smw + (kb & 1) * STG_W;
        if (kb < 7) stage_ldg(R, A, BT, m0, kb + 1, t);
#pragma unroll
        for (int ks = 0; ks < 2; ks++) {
            uint4 av[2];
#pragma unroll
            for (int mi = 0; mi < 2; mi++) {
                int mt = wm * 2 + mi;
                av[mi] = *(const uint4*)&buf[((mt * 2 + ks) * 32 + lane) * 4];
            }
#pragma unroll
            for (int nt8 = 0; nt8 < 8; nt8++) {
                int nt = wn * 8 + nt8;
                uint2 bv = *(const uint2*)&buf[2048 + ((nt * 2 + ks) * 32 + lane) * 2];
                mma_f16(acc[0][nt8], (const uint32_t*)&av[0], bv.x, bv.y);
                mma_f16(acc[1][nt8], (const uint32_t*)&av[1], bv.x, bv.y);
            }
        }
        if (kb < 7) {
            stage_sts(R, smw + ((kb + 1) & 1) * STG_W, t);
            __syncthreads();
        }
    }

    // ---------------- epilogue (+bias, +fused es/ed dots) ----------------
    float esp[2][2] = {{0.f, 0.f}, {0.f, 0.f}};
    float edp[2][2] = {{0.f, 0.f}, {0.f, 0.f}};
#pragma unroll
    for (int mi = 0; mi < 2; mi++) {
        int row = m0 + wm * 32 + mi * 16 + g;
#pragma unroll
        for (int nt8 = 0; nt8 < 8; nt8++) {
            int col = wn * 64 + nt8 * 8 + tig * 2;
            float a0 = acc[mi][nt8][0], a1 = acc[mi][nt8][1];
            float a2 = acc[mi][nt8][2], a3 = acc[mi][nt8][3];
            if (bias) {
                float b0 = __ldg(bias + col), b1 = __ldg(bias + col + 1);
                a0 += b0; a1 += b1; a2 += b0; a3 += b1;
            }
            *(__half2*)(C + (size_t)row * HIDDEN + col) = __floats2half2_rn(a0, a1);
            *(__half2*)(C + (size_t)(row + 8) * HIDDEN + col) = __floats2half2_rn(a2, a3);
            float s0 = __ldg(avS + col), s1 = __ldg(avS + col + 1);
            float d0 = __ldg(avD + col), d1 = __ldg(avD + col + 1);
            esp[mi][0] += a0 * s0 + a1 * s1;
            esp[mi][1] += a2 * s0 + a3 * s1;
            edp[mi][0] += a0 * d0 + a1 * d1;
            edp[mi][1] += a2 * d0 + a3 * d1;
        }
    }
#pragma unroll
    for (int o = 1; o <= 2; o <<= 1) {
#pragma unroll
        for (int mi = 0; mi < 2; mi++)
#pragma unroll
            for (int hv = 0; hv < 2; hv++) {
                esp[mi][hv] += __shfl_xor_sync(0xffffffffu, esp[mi][hv], o);
                edp[mi][hv] += __shfl_xor_sync(0xffffffffu, edp[mi][hv], o);
            }
    }
    if (tig == 0) {
#pragma unroll
        for (int mi = 0; mi < 2; mi++)
#pragma unroll
            for (int hv = 0; hv < 2; hv++) {
                int rl = wm * 32 + mi * 16 + hv * 8 + g;
                atomicAdd(&red[rl], esp[mi][hv]);
                atomicAdd(&red[128 + rl], edp[mi][hv]);
            }
    }
    __syncthreads();
    if (t < 128) {
        es[m0 + t] = red[t];
        ed[m0 + t] = red[128 + t];
    }
}

// ---------------- CSR build ----------------
__global__ void k_init_deg() {
    int i = blockIdx.x * blockDim.x + threadIdx.x;
    if (i < N_NODES) g_deg[i] = 1;
}
__global__ void k_count_deg(const int* __restrict__ dst, int E) {
    int e = blockIdx.x * blockDim.x + threadIdx.x;
    if (e < E) atomicAdd(&g_deg[dst[e]], 1);
}
__global__ void k_scan() {
    __shared__ int sh[1024];
    int t = threadIdx.x;
    int base = t * 64;
    int s = 0;
    for (int j = 0; j < 64; j++) s += g_deg[base + j];
    sh[t] = s;
    __syncthreads();
    for (int d = 1; d < 1024; d <<= 1) {
        int v = (t >= d) ? sh[t - d] : 0;
        __syncthreads();
        sh[t] += v;
        __syncthreads();
    }
    int run = sh[t] - s;
    for (int j = 0; j < 64; j++) {
        g_off[base + j] = run;
        run += g_deg[base + j];
    }
    if (t == 1023) g_off[N_NODES] = run;
}
__global__ void k_init_cur() {
    int i = blockIdx.x * blockDim.x + threadIdx.x;
    if (i < N_NODES) g_cur[i] = g_off[i];
}
__global__ void k_fill(const int* __restrict__ src, const int* __restrict__ dst, int E) {
    int e = blockIdx.x * blockDim.x + threadIdx.x;
    if (e < E) {
        int pos = atomicAdd(&g_cur[dst[e]], 1);
        g_csr[pos] = src[e];
    }
}
__global__ void k_selfloop() {
    int i = blockIdx.x * blockDim.x + threadIdx.x;
    if (i < N_NODES) g_csr[g_off[i + 1] - 1] = i;
}

// ---------------- embedding gather (writes half) ----------------
__global__ void k_embed(const int* __restrict__ nodes, const float* __restrict__ emb) {
    int idx = blockIdx.x * blockDim.x + threadIdx.x;
    if (idx < N_NODES * HIDDEN) {
        int n = idx >> 8;
        int c = idx & 255;
        g_x[idx] = __float2half(emb[(size_t)nodes[n] * HIDDEN + c]);
    }
}

// ---------------- scalar fp32 GEMM (compose / tail) ----------------
#define BM 64
#define BN 64
#define BK 16
__global__ void k_gemm(const float* __restrict__ A, const float* __restrict__ B,
                       const float* __restrict__ bias, float* __restrict__ C,
                       int M, int N, int K) {
    __shared__ float As[BM][BK];
    __shared__ float Bs[BK][BN + 1];
    int tid = threadIdx.y * 16 + threadIdx.x;
    int m0 = blockIdx.y * BM, n0 = blockIdx.x * BN;
    float acc[4][4] = {};
    for (int k0 = 0; k0 < K; k0 += BK) {
#pragma unroll
        for (int r = 0; r < 4; r++) {
            int e = tid + r * 256;
            int m = e / BK, k = e % BK;
            As[m][k] = (m0 + m < M) ? A[(size_t)(m0 + m) * K + k0 + k] : 0.f;
        }
#pragma unroll
        for (int r = 0; r < 4; r++) {
            int e = tid + r * 256;
            int k = e / BN, n = e % BN;
            Bs[k][n] = (n0 + n < N) ? B[(size_t)(k0 + k) * N + n0 + n] : 0.f;
        }
        __syncthreads();
#pragma unroll
        for (int kk = 0; kk < BK; kk++) {
            float ra[4], rb[4];
#pragma unroll
            for (int i = 0; i < 4; i++) ra[i] = As[threadIdx.y * 4 + i][kk];
#pragma unroll
            for (int j = 0; j < 4; j++) rb[j] = Bs[kk][threadIdx.x * 4 + j];
#pragma unroll
            for (int i = 0; i < 4; i++)
#pragma unroll
                for (int j = 0; j < 4; j++) acc[i][j] += ra[i] * rb[j];
        }
        __syncthreads();
    }
#pragma unroll
    for (int i = 0; i < 4; i++) {
        int m = m0 + threadIdx.y * 4 + i;
        if (m >= M) continue;
#pragma unroll
        for (int j = 0; j < 4; j++) {
            int n = n0 + threadIdx.x * 4 + j;
            if (n >= N) continue;
            float v = acc[i][j];
            if (bias) v += bias[n];
            C[(size_t)m * N + n] = v;
        }
    }
}

__device__ __forceinline__ float leaky(float v) {
    return v > 0.f ? v : NEG_SLOPE * v;
}

// ---------------- GAT aggregation: one warp per dst node (half I/O) ----------------
__global__ void k_agg(const __half* __restrict__ h, const float* __restrict__ bg,
                      __half* __restrict__ out) {
    int w = (blockIdx.x * blockDim.x + threadIdx.x) >> 5;
    int lane = threadIdx.x & 31;
    if (w >= N_NODES) return;
    int b0 = g_off[w], b1 = g_off[w + 1];
    float edv = g_ed[w];
    float m = -1e30f;
    for (int e = b0 + lane; e < b1; e += 32)
        m = fmaxf(m, leaky(g_es[g_csr[e]] + edv));
#pragma unroll
    for (int o = 16; o; o >>= 1) m = fmaxf(m, __shfl_xor_sync(0xffffffffu, m, o));
    float s = 0.f;
    for (int e = b0 + lane; e < b1; e += 32)
        s += __expf(leaky(g_es[g_csr[e]] + edv) - m);
#pragma unroll
    for (int o = 16; o; o >>= 1) s += __shfl_xor_sync(0xffffffffu, s, o);
    float inv = 1.f / (s + EPS_SM);
    float2 acc[4] = {};
    for (int e = b0; e < b1; e++) {
        int src = g_csr[e];
        float a = __expf(leaky(g_es[src] + edv) - m) * inv;
        const __half2* hr = (const __half2*)(h + (size_t)src * HIDDEN);
#pragma unroll
        for (int j = 0; j < 4; j++) {
            float2 f = __half22float2(hr[lane + 32 * j]);
            acc[j].x += a * f.x;
            acc[j].y += a * f.y;
        }
    }
    __half2* op = (__half2*)(out + (size_t)w * HIDDEN);
#pragma unroll
    for (int j = 0; j < 4; j++) {
        int c2 = lane + 32 * j;
        float2 b2 = ((const float2*)bg)[c2];
        op[c2] = __floats2half2_rn(fmaxf(acc[j].x + b2.x, 0.f),
                                   fmaxf(acc[j].y + b2.y, 0.f));
    }
}

// ---------------- mean pool (half input) ----------------
__global__ void k_pool_zero() {
    int i = blockIdx.x * blockDim.x + threadIdx.x;
    if (i < NUM_GRAPHS * HIDDEN) g_pool[i] = 0.f;
    if (i < NUM_GRAPHS) g_gcnt[i] = 0;
}
__global__ void k_counts(const int* __restrict__ batch) {
    int i = blockIdx.x * blockDim.x + threadIdx.x;
    if (i < N_NODES) atomicAdd(&g_gcnt[batch[i]], 1);
}
__global__ void k_pool(const __half* __restrict__ x, const int* __restrict__ batch) {
    __shared__ int shb[256];
    int c = threadIdx.x;
    int n0 = blockIdx.x * 256;
    shb[c] = batch[n0 + c];
    __syncthreads();
    float acc = 0.f;
    int cg = shb[0];
    for (int n = 0; n < 256; n++) {
        int g = shb[n];
        if (g != cg) {
            atomicAdd(&g_pool[cg * HIDDEN + c], acc);
            acc = 0.f;
            cg = g;
        }
        acc += __half2float(x[(size_t)(n0 + n) * HIDDEN + c]);
    }
    atomicAdd(&g_pool[cg * HIDDEN + c], acc);
}
__global__ void k_mean() {
    int i = blockIdx.x * blockDim.x + threadIdx.x;
    if (i < NUM_GRAPHS * HIDDEN) {
        float cnt = (float)g_gcnt[i >> 8];
        g_pool[i] /= fmaxf(cnt, 1.f);
    }
}

// ---------------- launch ----------------
extern "C" void kernel_launch(void* const* d_in, const int* in_sizes, int n_in,
                              void* d_out, int out_size) {
    const int*   nodes = (const int*)d_in[0];
    const int*   eidx  = (const int*)d_in[1];
    const int*   batch = (const int*)d_in[2];
    const float* emb   = (const float*)d_in[3];
    const float* Wg    = (const float*)d_in[4];
    const float* a_src = (const float*)d_in[5];
    const float* a_dst = (const float*)d_in[6];
    const float* bg    = (const float*)d_in[7];
    const float* Wl    = (const float*)d_in[8];
    const float* bl    = (const float*)d_in[9];
    const float* Wout  = (const float*)d_in[10];
    const float* bout  = (const float*)d_in[11];

    const int E = in_sizes[1] / 2;
    const int* src = eidx;
    const int* dst = eidx + E;

    __half *dx, *dh, *dt, *dWT;
    float *dpool, *des, *ded, *dWc, *dbc, *dsmall;
    cudaGetSymbolAddress((void**)&dx, g_x);
    cudaGetSymbolAddress((void**)&dh, g_h);
    cudaGetSymbolAddress((void**)&dt, g_t);
    cudaGetSymbolAddress((void**)&dpool, g_pool);
    cudaGetSymbolAddress((void**)&dWT, g_WT);
    cudaGetSymbolAddress((void**)&des, g_es);
    cudaGetSymbolAddress((void**)&ded, g_ed);
    cudaGetSymbolAddress((void**)&dWc, g_Wc);
    cudaGetSymbolAddress((void**)&dbc, g_bc);
    cudaGetSymbolAddress((void**)&dsmall, g_small);

    cudaFuncSetAttribute(k_gemm_mma, cudaFuncAttributeMaxDynamicSharedMemorySize,
                         SMEM_MMA);

    // CSR build
    k_init_deg<<<N_NODES / 256, 256>>>();
    k_count_deg<<<(E + 255) / 256, 256>>>(dst, E);
    k_scan<<<1, 1024>>>();
    k_init_cur<<<N_NODES / 256, 256>>>();
    k_fill<<<(E + 255) / 256, 256>>>(src, dst, E);
    k_selfloop<<<N_NODES / 256, 256>>>();

    // weight prep: Wc_l = Wl_l @ Wg_{l+1} (fp32), bc_l = bl_l @ Wg_{l+1}
    dim3 blk(16, 16);
    dim3 grd_cmp(HIDDEN / BN, HIDDEN / BM);
    k_gemm<<<grd_cmp, blk>>>(Wl, Wg + HIDDEN * HIDDEN, nullptr, dWc,
                             HIDDEN, HIDDEN, HIDDEN);
    k_gemm<<<grd_cmp, blk>>>(Wl + HIDDEN * HIDDEN, Wg + 2 * HIDDEN * HIDDEN, nullptr,
                             dWc + HIDDEN * HIDDEN, HIDDEN, HIDDEN, HIDDEN);
    k_bias_c<<<2, HIDDEN>>>(bl, Wg);
    k_transpose0<<<(HIDDEN * HIDDEN) / 256, 256>>>(Wg);
    k_transpose_c<<<(2 * HIDDEN * HIDDEN) / 256, 256>>>();

    // embedding
    k_embed<<<(N_NODES * HIDDEN) / 256, 256>>>(nodes, emb);

    const int warp_blocks = (N_NODES * 32) / 256;
    const int GRID = N_NODES / 128;

    // layer 0: h1 = x0 @ Wg0 (fused es/ed)
    k_gemm_mma<<<GRID, 512, SMEM_MMA>>>(dx, dWT, dh, nullptr,
                                        a_src, a_dst, des, ded);
    k_agg<<<warp_blocks, 256>>>(dh, bg, dt);

    // layer 1: h2 = t1 @ Wc0 + bc0 (fused es/ed)
    k_gemm_mma<<<GRID, 512, SMEM_MMA>>>(dt, dWT + HIDDEN * HIDDEN, dh, dbc,
                                        a_src + HIDDEN, a_dst + HIDDEN, des, ded);
    k_agg<<<warp_blocks, 256>>>(dh, bg + HIDDEN, dx);   // reuse g_x as t2

    // layer 2: h3 = t2 @ Wc1 + bc1 (fused es/ed)
    k_gemm_mma<<<GRID, 512, SMEM_MMA>>>(dx, dWT + 2 * HIDDEN * HIDDEN, dh,
                                        dbc + HIDDEN,
                                        a_src + 2 * HIDDEN, a_dst + 2 * HIDDEN,
                                        des, ded);
    k_agg<<<warp_blocks, 256>>>(dh, bg + 2 * HIDDEN, dt);   // t3

    // mean pool over t3
    k_pool_zero<<<(NUM_GRAPHS * HIDDEN + 255) / 256, 256>>>();
    k_counts<<<N_NODES / 256, 256>>>(batch);
    k_pool<<<N_NODES / 256, 256>>>(dt, batch);
    k_mean<<<(NUM_GRAPHS * HIDDEN + 255) / 256, 256>>>();

    // small = pooled @ Wl2 + bl2   [64,256]
    dim3 grd_sm(HIDDEN / BN, (NUM_GRAPHS + BM - 1) / BM);
    k_gemm<<<grd_sm, blk>>>(dpool, Wl + 2 * HIDDEN * HIDDEN, bl + 2 * HIDDEN,
                            dsmall, NUM_GRAPHS, HIDDEN, HIDDEN);

    // out = small @ Wout + bout   [64,50000]
    dim3 grd_out((VOCAB + BN - 1) / BN, (NUM_GRAPHS + BM - 1) / BM);
    k_gemm<<<grd_out, blk>>>(dsmall, Wout, bout, (float*)d_out,
                             NUM_GRAPHS, VOCAB, HIDDEN);
}

// round 6
// speedup vs baseline: 2.8378x; 1.0002x over previous
#include <cuda_runtime.h>
#include <cuda_fp16.h>
#include <cstdint>
#include <math.h>

#define N_NODES   65536
#define HIDDEN    256
#define NUM_GRAPHS 64
#define VOCAB     50000
#define LAYERS    3
#define MAX_E     1114112
#define NEG_SLOPE 0.2f
#define EPS_SM    1e-16f

// ---------------- scratch ----------------
__device__ __half g_x[N_NODES * HIDDEN];
__device__ __half g_h[N_NODES * HIDDEN];
__device__ __half g_t[N_NODES * HIDDEN];
__device__ __half g_WT[LAYERS * HIDDEN * HIDDEN];
__device__ float g_Wc[2 * HIDDEN * HIDDEN];
__device__ float g_bc[2 * HIDDEN];
__device__ float g_es[N_NODES];
__device__ float g_ed[N_NODES];
__device__ int   g_deg[N_NODES];
__device__ int   g_off[N_NODES + 1];
__device__ int   g_cur[N_NODES];
__device__ int   g_csr[MAX_E];
__device__ float g_pool[NUM_GRAPHS * HIDDEN];
__device__ float g_small[NUM_GRAPHS * HIDDEN];
__device__ int   g_gcnt[NUM_GRAPHS];

__device__ __forceinline__ void mma_f16(float* c, const uint32_t* a,
                                        uint32_t b0, uint32_t b1) {
    asm volatile(
        "mma.sync.aligned.m16n8k16.row.col.f32.f16.f16.f32 "
        "{%0,%1,%2,%3}, {%4,%5,%6,%7}, {%8,%9}, {%0,%1,%2,%3};\n"
        : "+f"(c[0]), "+f"(c[1]), "+f"(c[2]), "+f"(c[3])
        : "r"(a[0]), "r"(a[1]), "r"(a[2]), "r"(a[3]), "r"(b0), "r"(b1));
}

// ---------------- weight transposes ----------------
__global__ void k_transpose0(const float* __restrict__ Wg) {
    int i = blockIdx.x * 256 + threadIdx.x;
    int n = i >> 8, k = i & 255;
    g_WT[i] = __float2half(Wg[k * HIDDEN + n]);
}
__global__ void k_transpose_c() {
    int i = blockIdx.x * 256 + threadIdx.x;
    int which = i >> 16;
    int nk = i & 65535;
    int n = nk >> 8, k = nk & 255;
    g_WT[(1 + which) * HIDDEN * HIDDEN + nk] =
        __float2half(g_Wc[which * HIDDEN * HIDDEN + k * HIDDEN + n]);
}
__global__ void k_bias_c(const float* __restrict__ bl, const float* __restrict__ Wg) {
    int which = blockIdx.x;
    int n = threadIdx.x;
    const float* b = bl + which * HIDDEN;
    const float* W = Wg + (which + 1) * HIDDEN * HIDDEN;
    float s = 0.f;
    for (int k = 0; k < HIDDEN; k++) s += b[k] * W[k * HIDDEN + n];
    g_bc[which * HIDDEN + n] = s;
}

// ============ fp16 mma GEMM ============
#define STG_W 6144
#define RED_W 12288
#define SMEM_MMA (RED_W * 4 + 1024)

struct StageRegs { uint4 a, b0, b1; };

__device__ __forceinline__ void stage_ldg(StageRegs& R, const __half* __restrict__ A,
                                          const __half* __restrict__ BT,
                                          int m0, int kb, int t) {
    {
        int row = t >> 2, j = t & 3;
        R.a = *(const uint4*)(A + (size_t)(m0 + row) * HIDDEN + kb * 32 + j * 8);
    }
#pragma unroll
    for (int i = 0; i < 2; i++) {
        int f = t + 512 * i;
        int n = f >> 2, j = f & 3;
        uint4 v = *(const uint4*)(BT + (size_t)n * HIDDEN + kb * 32 + j * 8);
        if (i == 0) R.b0 = v; else R.b1 = v;
    }
}

__device__ __forceinline__ void stage_sts(const StageRegs& R, uint32_t* __restrict__ buf,
                                          int t) {
    {
        int row = t >> 2, j = t & 3;
        int mt = row >> 4, mr = row & 15, g = mr & 7;
        int ks = j >> 1, reg = (mr >> 3) + 2 * (j & 1);
        uint32_t wb = ((mt * 2 + ks) * 32 + g * 4) * 4 + reg;
        buf[wb] = R.a.x; buf[wb + 4] = R.a.y; buf[wb + 8] = R.a.z; buf[wb + 12] = R.a.w;
    }
#pragma unroll
    for (int i = 0; i < 2; i++) {
        int f = t + 512 * i;
        int n = f >> 2, j = f & 3;
        int nt = n >> 3, g = n & 7;
        int ks = j >> 1, reg = j & 1;
        uint4 v = (i == 0) ? R.b0 : R.b1;
        uint32_t wb = 2048 + ((nt * 2 + ks) * 32 + g * 4) * 2 + reg;
        buf[wb] = v.x; buf[wb + 2] = v.y; buf[wb + 4] = v.z; buf[wb + 6] = v.w;
    }
}

__global__ void __launch_bounds__(512, 1) k_gemm_mma(
    const __half* __restrict__ A, const __half* __restrict__ BT,
    __half* __restrict__ C, const float* __restrict__ bias,
    const float* __restrict__ avS, const float* __restrict__ avD,
    float* __restrict__ es, float* __restrict__ ed)
{
    extern __shared__ uint32_t smw[];
    float* red = (float*)(smw + RED_W);
    const int t = threadIdx.x;
    const int lane = t & 31, wid = t >> 5;
    const int wm = wid & 3, wn = wid >> 2;
    const int m0 = blockIdx.x * 128;
    const int g = lane >> 2, tig = lane & 3;

    if (t < 256) red[t] = 0.f;

    float acc[2][8][4];
#pragma unroll
    for (int i = 0; i < 2; i++)
#pragma unroll
        for (int j = 0; j < 8; j++)
#pragma unroll
            for (int k = 0; k < 4; k++) acc[i][j][k] = 0.f;

    StageRegs R;
    stage_ldg(R, A, BT, m0, 0, t);
    stage_sts(R, smw, t);
    __syncthreads();

#pragma unroll 1
    for (int kb = 0; kb < 8; kb++) {
        const uint32_t* buf = smw + (kb & 1) * STG_W;
        if (kb < 7) stage_ldg(R, A, BT, m0, kb + 1, t);
#pragma unroll
        for (int ks = 0; ks < 2; ks++) {
            uint4 av[2];
#pragma unroll
            for (int mi = 0; mi < 2; mi++) {
                int mt = wm * 2 + mi;
                av[mi] = *(const uint4*)&buf[((mt * 2 + ks) * 32 + lane) * 4];
            }
#pragma unroll
            for (int nt8 = 0; nt8 < 8; nt8++) {
                int nt = wn * 8 + nt8;
                uint2 bv = *(const uint2*)&buf[2048 + ((nt * 2 + ks) * 32 + lane) * 2];
                mma_f16(acc[0][nt8], (const uint32_t*)&av[0], bv.x, bv.y);
                mma_f16(acc[1][nt8], (const uint32_t*)&av[1], bv.x, bv.y);
            }
        }
        if (kb < 7) {
            stage_sts(R, smw + ((kb + 1) & 1) * STG_W, t);
            __syncthreads();
        }
    }

    // ---------------- epilogue (+bias, +fused es/ed dots) ----------------
    float esp[2][2] = {{0.f, 0.f}, {0.f, 0.f}};
    float edp[2][2] = {{0.f, 0.f}, {0.f, 0.f}};
#pragma unroll
    for (int mi = 0; mi < 2; mi++) {
        int row = m0 + wm * 32 + mi * 16 + g;
#pragma unroll
        for (int nt8 = 0; nt8 < 8; nt8++) {
            int col = wn * 64 + nt8 * 8 + tig * 2;
            float a0 = acc[mi][nt8][0], a1 = acc[mi][nt8][1];
            float a2 = acc[mi][nt8][2], a3 = acc[mi][nt8][3];
            if (bias) {
                float b0 = __ldg(bias + col), b1 = __ldg(bias + col + 1);
                a0 += b0; a1 += b1; a2 += b0; a3 += b1;
            }
            *(__half2*)(C + (size_t)row * HIDDEN + col) = __floats2half2_rn(a0, a1);
            *(__half2*)(C + (size_t)(row + 8) * HIDDEN + col) = __floats2half2_rn(a2, a3);
            float s0 = __ldg(avS + col), s1 = __ldg(avS + col + 1);
            float d0 = __ldg(avD + col), d1 = __ldg(avD + col + 1);
            esp[mi][0] += a0 * s0 + a1 * s1;
            esp[mi][1] += a2 * s0 + a3 * s1;
            edp[mi][0] += a0 * d0 + a1 * d1;
            edp[mi][1] += a2 * d0 + a3 * d1;
        }
    }
#pragma unroll
    for (int o = 1; o <= 2; o <<= 1) {
#pragma unroll
        for (int mi = 0; mi < 2; mi++)
#pragma unroll
            for (int hv = 0; hv < 2; hv++) {
                esp[mi][hv] += __shfl_xor_sync(0xffffffffu, esp[mi][hv], o);
                edp[mi][hv] += __shfl_xor_sync(0xffffffffu, edp[mi][hv], o);
            }
    }
    if (tig == 0) {
#pragma unroll
        for (int mi = 0; mi < 2; mi++)
#pragma unroll
            for (int hv = 0; hv < 2; hv++) {
                int rl = wm * 32 + mi * 16 + hv * 8 + g;
                atomicAdd(&red[rl], esp[mi][hv]);
                atomicAdd(&red[128 + rl], edp[mi][hv]);
            }
    }
    __syncthreads();
    if (t < 128) {
        es[m0 + t] = red[t];
        ed[m0 + t] = red[128 + t];
    }
}

// ---------------- CSR build ----------------
__global__ void k_init_deg() {
    int i = blockIdx.x * blockDim.x + threadIdx.x;
    if (i < N_NODES) g_deg[i] = 1;
}
__global__ void k_count_deg(const int* __restrict__ dst, int E) {
    int e = blockIdx.x * blockDim.x + threadIdx.x;
    if (e < E) atomicAdd(&g_deg[dst[e]], 1);
}
__global__ void k_scan() {
    __shared__ int sh[1024];
    int t = threadIdx.x;
    int base = t * 64;
    int s = 0;
    for (int j = 0; j < 64; j++) s += g_deg[base + j];
    sh[t] = s;
    __syncthreads();
    for (int d = 1; d < 1024; d <<= 1) {
        int v = (t >= d) ? sh[t - d] : 0;
        __syncthreads();
        sh[t] += v;
        __syncthreads();
    }
    int run = sh[t] - s;
    for (int j = 0; j < 64; j++) {
        g_off[base + j] = run;
        run += g_deg[base + j];
    }
    if (t == 1023) g_off[N_NODES] = run;
}
__global__ void k_init_cur() {
    int i = blockIdx.x * blockDim.x + threadIdx.x;
    if (i < N_NODES) g_cur[i] = g_off[i];
}
__global__ void k_fill(const int* __restrict__ src, const int* __restrict__ dst, int E) {
    int e = blockIdx.x * blockDim.x + threadIdx.x;
    if (e < E) {
        int pos = atomicAdd(&g_cur[dst[e]], 1);
        g_csr[pos] = src[e];
    }
}
__global__ void k_selfloop() {
    int i = blockIdx.x * blockDim.x + threadIdx.x;
    if (i < N_NODES) g_csr[g_off[i + 1] - 1] = i;
}

// ---------------- embedding gather ----------------
__global__ void k_embed(const int* __restrict__ nodes, const float* __restrict__ emb) {
    int idx = blockIdx.x * blockDim.x + threadIdx.x;
    if (idx < N_NODES * HIDDEN) {
        int n = idx >> 8;
        int c = idx & 255;
        g_x[idx] = __float2half(emb[(size_t)nodes[n] * HIDDEN + c]);
    }
}

// ---------------- scalar fp32 GEMM (compose / tail) ----------------
#define BM 64
#define BN 64
#define BK 16
__global__ void k_gemm(const float* __restrict__ A, const float* __restrict__ B,
                       const float* __restrict__ bias, float* __restrict__ C,
                       int M, int N, int K) {
    __shared__ float As[BM][BK];
    __shared__ float Bs[BK][BN + 1];
    int tid = threadIdx.y * 16 + threadIdx.x;
    int m0 = blockIdx.y * BM, n0 = blockIdx.x * BN;
    float acc[4][4] = {};
    for (int k0 = 0; k0 < K; k0 += BK) {
#pragma unroll
        for (int r = 0; r < 4; r++) {
            int e = tid + r * 256;
            int m = e / BK, k = e % BK;
            As[m][k] = (m0 + m < M) ? A[(size_t)(m0 + m) * K + k0 + k] : 0.f;
        }
#pragma unroll
        for (int r = 0; r < 4; r++) {
            int e = tid + r * 256;
            int k = e / BN, n = e % BN;
            Bs[k][n] = (n0 + n < N) ? B[(size_t)(k0 + k) * N + n0 + n] : 0.f;
        }
        __syncthreads();
#pragma unroll
        for (int kk = 0; kk < BK; kk++) {
            float ra[4], rb[4];
#pragma unroll
            for (int i = 0; i < 4; i++) ra[i] = As[threadIdx.y * 4 + i][kk];
#pragma unroll
            for (int j = 0; j < 4; j++) rb[j] = Bs[kk][threadIdx.x * 4 + j];
#pragma unroll
            for (int i = 0; i < 4; i++)
#pragma unroll
                for (int j = 0; j < 4; j++) acc[i][j] += ra[i] * rb[j];
        }
        __syncthreads();
    }
#pragma unroll
    for (int i = 0; i < 4; i++) {
        int m = m0 + threadIdx.y * 4 + i;
        if (m >= M) continue;
#pragma unroll
        for (int j = 0; j < 4; j++) {
            int n = n0 + threadIdx.x * 4 + j;
            if (n >= N) continue;
            float v = acc[i][j];
            if (bias) v += bias[n];
            C[(size_t)m * N + n] = v;
        }
    }
}

__device__ __forceinline__ float leaky(float v) {
    return v > 0.f ? v : NEG_SLOPE * v;
}

__device__ __forceinline__ void fma8(float* acc, uint4 r, float a) {
    const __half2* p = (const __half2*)&r;
#pragma unroll
    for (int j = 0; j < 4; j++) {
        float2 f = __half22float2(p[j]);
        acc[2 * j]     += a * f.x;
        acc[2 * j + 1] += a * f.y;
    }
}

// ---------------- GAT aggregation: one warp per dst node ----------------
// pass 3: lane owns 8 contiguous halves (one LDG.128 per edge), unrolled x4.
__global__ void k_agg(const __half* __restrict__ h, const float* __restrict__ bg,
                      __half* __restrict__ out) {
    int w = (blockIdx.x * blockDim.x + threadIdx.x) >> 5;
    int lane = threadIdx.x & 31;
    if (w >= N_NODES) return;
    int b0 = g_off[w], b1 = g_off[w + 1];
    float edv = g_ed[w];

    // online max+sum, lane-strided
    float m = -1e30f, s = 0.f;
    for (int e = b0 + lane; e < b1; e += 32) {
        float v = leaky(g_es[g_csr[e]] + edv);
        float mn = fmaxf(m, v);
        s = s * __expf(m - mn) + __expf(v - mn);
        m = mn;
    }
#pragma unroll
    for (int o = 16; o; o >>= 1) {
        float mo = __shfl_xor_sync(0xffffffffu, m, o);
        float so = __shfl_xor_sync(0xffffffffu, s, o);
        float mn = fmaxf(m, mo);
        s = s * __expf(m - mn) + so * __expf(mo - mn);
        m = mn;
    }
    float inv = 1.f / (s + EPS_SM);

    // weighted feature sum
    float acc[8] = {};
    const __half* hl = h + lane * 8;
#pragma unroll 1
    for (int e = b0; e < b1; e += 4) {
        int n = b1 - e;
        int i0 = g_csr[e];
        int i1 = g_csr[n > 1 ? e + 1 : e];
        int i2 = g_csr[n > 2 ? e + 2 : e];
        int i3 = g_csr[n > 3 ? e + 3 : e];
        float a0 = __expf(leaky(g_es[i0] + edv) - m) * inv;
        float a1 = (n > 1) ? __expf(leaky(g_es[i1] + edv) - m) * inv : 0.f;
        float a2 = (n > 2) ? __expf(leaky(g_es[i2] + edv) - m) * inv : 0.f;
        float a3 = (n > 3) ? __expf(leaky(g_es[i3] + edv) - m) * inv : 0.f;
        uint4 r0 = *(const uint4*)(hl + (size_t)i0 * HIDDEN);
        uint4 r1 = *(const uint4*)(hl + (size_t)i1 * HIDDEN);
        uint4 r2 = *(const uint4*)(hl + (size_t)i2 * HIDDEN);
        uint4 r3 = *(const uint4*)(hl + (size_t)i3 * HIDDEN);
        fma8(acc, r0, a0);
        fma8(acc, r1, a1);
        fma8(acc, r2, a2);
        fma8(acc, r3, a3);
    }

    // +bias, relu, store (lane owns cols [lane*8, lane*8+8))
    uint4 ov;
    __half2* op = (__half2*)&ov;
#pragma unroll
    for (int j = 0; j < 4; j++) {
        int c = lane * 8 + 2 * j;
        float2 b2 = *(const float2*)(bg + c);
        op[j] = __floats2half2_rn(fmaxf(acc[2 * j] + b2.x, 0.f),
                                  fmaxf(acc[2 * j + 1] + b2.y, 0.f));
    }
    *(uint4*)(out + (size_t)w * HIDDEN + lane * 8) = ov;
}

// ---------------- mean pool ----------------
__global__ void k_pool_zero() {
    int i = blockIdx.x * blockDim.x + threadIdx.x;
    if (i < NUM_GRAPHS * HIDDEN) g_pool[i] = 0.f;
    if (i < NUM_GRAPHS) g_gcnt[i] = 0;
}
__global__ void k_counts(const int* __restrict__ batch) {
    int i = blockIdx.x * blockDim.x + threadIdx.x;
    if (i < N_NODES) atomicAdd(&g_gcnt[batch[i]], 1);
}
__global__ void k_pool(const __half* __restrict__ x, const int* __restrict__ batch) {
    __shared__ int shb[256];
    int c = threadIdx.x;
    int n0 = blockIdx.x * 256;
    shb[c] = batch[n0 + c];
    __syncthreads();
    float acc = 0.f;
    int cg = shb[0];
    for (int n = 0; n < 256; n++) {
        int g = shb[n];
        if (g != cg) {
            atomicAdd(&g_pool[cg * HIDDEN + c], acc);
            acc = 0.f;
            cg = g;
        }
        acc += __half2float(x[(size_t)(n0 + n) * HIDDEN + c]);
    }
    atomicAdd(&g_pool[cg * HIDDEN + c], acc);
}
__global__ void k_mean() {
    int i = blockIdx.x * blockDim.x + threadIdx.x;
    if (i < NUM_GRAPHS * HIDDEN) {
        float cnt = (float)g_gcnt[i >> 8];
        g_pool[i] /= fmaxf(cnt, 1.f);
    }
}

// ---------------- launch ----------------
extern "C" void kernel_launch(void* const* d_in, const int* in_sizes, int n_in,
                              void* d_out, int out_size) {
    const int*   nodes = (const int*)d_in[0];
    const int*   eidx  = (const int*)d_in[1];
    const int*   batch = (const int*)d_in[2];
    const float* emb   = (const float*)d_in[3];
    const float* Wg    = (const float*)d_in[4];
    const float* a_src = (const float*)d_in[5];
    const float* a_dst = (const float*)d_in[6];
    const float* bg    = (const float*)d_in[7];
    const float* Wl    = (const float*)d_in[8];
    const float* bl    = (const float*)d_in[9];
    const float* Wout  = (const float*)d_in[10];
    const float* bout  = (const float*)d_in[11];

    const int E = in_sizes[1] / 2;
    const int* src = eidx;
    const int* dst = eidx + E;

    __half *dx, *dh, *dt, *dWT;
    float *dpool, *des, *ded, *dWc, *dbc, *dsmall;
    cudaGetSymbolAddress((void**)&dx, g_x);
    cudaGetSymbolAddress((void**)&dh, g_h);
    cudaGetSymbolAddress((void**)&dt, g_t);
    cudaGetSymbolAddress((void**)&dpool, g_pool);
    cudaGetSymbolAddress((void**)&dWT, g_WT);
    cudaGetSymbolAddress((void**)&des, g_es);
    cudaGetSymbolAddress((void**)&ded, g_ed);
    cudaGetSymbolAddress((void**)&dWc, g_Wc);
    cudaGetSymbolAddress((void**)&dbc, g_bc);
    cudaGetSymbolAddress((void**)&dsmall, g_small);

    cudaFuncSetAttribute(k_gemm_mma, cudaFuncAttributeMaxDynamicSharedMemorySize,
                         SMEM_MMA);

    // CSR build
    k_init_deg<<<N_NODES / 256, 256>>>();
    k_count_deg<<<(E + 255) / 256, 256>>>(dst, E);
    k_scan<<<1, 1024>>>();
    k_init_cur<<<N_NODES / 256, 256>>>();
    k_fill<<<(E + 255) / 256, 256>>>(src, dst, E);
    k_selfloop<<<N_NODES / 256, 256>>>();

    // weight prep
    dim3 blk(16, 16);
    dim3 grd_cmp(HIDDEN / BN, HIDDEN / BM);
    k_gemm<<<grd_cmp, blk>>>(Wl, Wg + HIDDEN * HIDDEN, nullptr, dWc,
                             HIDDEN, HIDDEN, HIDDEN);
    k_gemm<<<grd_cmp, blk>>>(Wl + HIDDEN * HIDDEN, Wg + 2 * HIDDEN * HIDDEN, nullptr,
                             dWc + HIDDEN * HIDDEN, HIDDEN, HIDDEN, HIDDEN);
    k_bias_c<<<2, HIDDEN>>>(bl, Wg);
    k_transpose0<<<(HIDDEN * HIDDEN) / 256, 256>>>(Wg);
    k_transpose_c<<<(2 * HIDDEN * HIDDEN) / 256, 256>>>();

    // embedding
    k_embed<<<(N_NODES * HIDDEN) / 256, 256>>>(nodes, emb);

    const int warp_blocks = (N_NODES * 32) / 256;
    const int GRID = N_NODES / 128;

    // layer 0
    k_gemm_mma<<<GRID, 512, SMEM_MMA>>>(dx, dWT, dh, nullptr,
                                        a_src, a_dst, des, ded);
    k_agg<<<warp_blocks, 256>>>(dh, bg, dt);

    // layer 1
    k_gemm_mma<<<GRID, 512, SMEM_MMA>>>(dt, dWT + HIDDEN * HIDDEN, dh, dbc,
                                        a_src + HIDDEN, a_dst + HIDDEN, des, ded);
    k_agg<<<warp_blocks, 256>>>(dh, bg + HIDDEN, dx);

    // layer 2
    k_gemm_mma<<<GRID, 512, SMEM_MMA>>>(dx, dWT + 2 * HIDDEN * HIDDEN, dh,
                                        dbc + HIDDEN,
                                        a_src + 2 * HIDDEN, a_dst + 2 * HIDDEN,
                                        des, ded);
    k_agg<<<warp_blocks, 256>>>(dh, bg + 2 * HIDDEN, dt);

    // mean pool over t3
    k_pool_zero<<<(NUM_GRAPHS * HIDDEN + 255) / 256, 256>>>();
    k_counts<<<N_NODES / 256, 256>>>(batch);
    k_pool<<<N_NODES / 256, 256>>>(dt, batch);
    k_mean<<<(NUM_GRAPHS * HIDDEN + 255) / 256, 256>>>();

    // small = pooled @ Wl2 + bl2
    dim3 grd_sm(HIDDEN / BN, (NUM_GRAPHS + BM - 1) / BM);
    k_gemm<<<grd_sm, blk>>>(dpool, Wl + 2 * HIDDEN * HIDDEN, bl + 2 * HIDDEN,
                            dsmall, NUM_GRAPHS, HIDDEN, HIDDEN);

    // out = small @ Wout + bout
    dim3 grd_out((VOCAB + BN - 1) / BN, (NUM_GRAPHS + BM - 1) / BM);
    k_gemm<<<grd_out, blk>>>(dsmall, Wout, bout, (float*)d_out,
                             NUM_GRAPHS, VOCAB, HIDDEN);
}